// round 2
// baseline (speedup 1.0000x reference)
#include <cuda_runtime.h>
#include <cstdint>
#include <cmath>

// Problem constants (fixed by the dataset)
#define B_ 64
#define S_ 512
#define D_ 1024
#define H_ 1024
#define G_ 4096   // 4*H

// -------- scratch (device globals; no allocation allowed) --------
__device__ float g_xw[(size_t)S_ * B_ * G_];   // (S, B, 4H) precomputed x@W + bias (512 MB)
__device__ float g_h2[2][B_ * H_];             // double-buffered hidden state
__device__ float g_c[B_ * H_];                 // cell state
__device__ unsigned g_count;                   // grid-barrier arrival counter
__device__ unsigned g_gen;                     // grid-barrier generation

// -------- init: zero state + barrier vars (graph replays must be deterministic) --------
__global__ void init_state() {
    int i = blockIdx.x * blockDim.x + threadIdx.x;
    g_h2[0][i] = 0.f;
    g_h2[1][i] = 0.f;
    g_c[i] = 0.f;
    if (i == 0) { g_count = 0; g_gen = 0; }
}

// -------- GEMM 1: g_xw[t*B+b, n] = sum_k x[b,t,k] * W[k,n] + bias[n] --------
// Classic fp32 SGEMM: 128x128 block tile, BK=8, 256 threads, 8x8 microtile.
__global__ __launch_bounds__(256) void gemm_xw(const float* __restrict__ x,
                                               const float* __restrict__ W,
                                               const float* __restrict__ bias) {
    const int BK = 8;
    __shared__ float As[BK][128];   // A^T tile: As[k][m]
    __shared__ float Bs[BK][128];   // B tile:   Bs[k][n]

    int tid = threadIdx.x;
    int m0 = blockIdx.y * 128;
    int n0 = blockIdx.x * 128;
    int tx = tid & 15;   // n microtile index (8 cols each)
    int ty = tid >> 4;   // m microtile index (8 rows each)

    int arow = tid >> 1;
    int acol = (tid & 1) * 4;
    int gm = m0 + arow;           // global row m = t*B + b
    int t_ = gm >> 6;             // / 64
    int b_ = gm & 63;             // % 64
    const float* aptr = x + ((size_t)b_ * S_ + t_) * D_ + acol;

    int brow = tid >> 5;
    int bcol = (tid & 31) * 4;
    const float* bptr = W + (size_t)brow * G_ + n0 + bcol;

    float acc[8][8];
#pragma unroll
    for (int i = 0; i < 8; i++)
#pragma unroll
        for (int j = 0; j < 8; j++) acc[i][j] = 0.f;

    for (int k0 = 0; k0 < D_; k0 += BK) {
        float4 av = *(const float4*)(aptr + k0);
        As[acol + 0][arow] = av.x;
        As[acol + 1][arow] = av.y;
        As[acol + 2][arow] = av.z;
        As[acol + 3][arow] = av.w;
        float4 bv = *(const float4*)(bptr + (size_t)k0 * G_);
        *(float4*)&Bs[brow][bcol] = bv;
        __syncthreads();
#pragma unroll
        for (int kk = 0; kk < BK; kk++) {
            float ra[8], rb[8];
            *(float4*)&ra[0] = *(const float4*)&As[kk][ty * 8];
            *(float4*)&ra[4] = *(const float4*)&As[kk][ty * 8 + 4];
            *(float4*)&rb[0] = *(const float4*)&Bs[kk][tx * 8];
            *(float4*)&rb[4] = *(const float4*)&Bs[kk][tx * 8 + 4];
#pragma unroll
            for (int i = 0; i < 8; i++)
#pragma unroll
                for (int j = 0; j < 8; j++)
                    acc[i][j] += ra[i] * rb[j];
        }
        __syncthreads();
    }

    float4 bias0 = *(const float4*)&bias[n0 + tx * 8];
    float4 bias1 = *(const float4*)&bias[n0 + tx * 8 + 4];
#pragma unroll
    for (int i = 0; i < 8; i++) {
        size_t row = (size_t)(m0 + ty * 8 + i);
        float4 v0, v1;
        v0.x = acc[i][0] + bias0.x; v0.y = acc[i][1] + bias0.y;
        v0.z = acc[i][2] + bias0.z; v0.w = acc[i][3] + bias0.w;
        v1.x = acc[i][4] + bias1.x; v1.y = acc[i][5] + bias1.y;
        v1.z = acc[i][6] + bias1.z; v1.w = acc[i][7] + bias1.w;
        *(float4*)&g_xw[row * G_ + n0 + tx * 8]     = v0;
        *(float4*)&g_xw[row * G_ + n0 + tx * 8 + 4] = v1;
    }
}

// -------- persistent recurrence kernel --------
// 128 CTAs (all co-resident), each owns an 8-wide j-tile of H.
// Per step: compute gates[b, {i,f,g,o} x 8 cols] = h @ U  (64x32 tile, K=1024),
// then fused cell update, then one grid barrier.
#define NBLK 128

__global__ __launch_bounds__(256, 1) void lstm_recur(const float* __restrict__ U,
                                                     float* __restrict__ out,
                                                     float* __restrict__ hT,
                                                     float* __restrict__ cT) {
    __shared__ float As[16][64];    // h^T tile: As[k][b]
    __shared__ float Us[16][32];    // U tile:   Us[k][n_local]  (4 gates x 8 cols)
    __shared__ float Gs[64][32];    // gate sums

    const int tid = threadIdx.x;
    const int j0 = blockIdx.x * 8;              // owned column tile of H

    // inner-loop thread mapping: 16(m) x 16(n/2)
    const int ty = tid >> 4;       // m group: rows ty*4 .. ty*4+3
    const int tx = tid & 15;       // n group: cols tx*2, tx*2+1

    // h staging: thread -> (b = tid>>2, k offset = (tid&3)*4), float4
    const int ab = tid >> 2;
    const int ak = (tid & 3) * 4;

    // U staging: thread -> (k row = tid>>4, n_local pair = (tid&15)*2), float2
    const int bk = tid >> 4;
    const int nl = (tid & 15) * 2;
    const int gate = nl >> 3;
    const int jj_u = nl & 7;
    const int ucol = gate * H_ + j0 + jj_u;     // global gate-space column

    unsigned gen = 0;

    for (int t = 0; t < S_; t++) {
        const float* __restrict__ h = g_h2[t & 1];
        float* __restrict__ hnext = g_h2[(t + 1) & 1];

        float acc00 = 0.f, acc01 = 0.f, acc10 = 0.f, acc11 = 0.f;
        float acc20 = 0.f, acc21 = 0.f, acc30 = 0.f, acc31 = 0.f;

        for (int k0 = 0; k0 < H_; k0 += 16) {
            float4 av = *(const float4*)&h[ab * H_ + k0 + ak];
            As[ak + 0][ab] = av.x;
            As[ak + 1][ab] = av.y;
            As[ak + 2][ab] = av.z;
            As[ak + 3][ab] = av.w;
            float2 uv = *(const float2*)&U[(size_t)(k0 + bk) * G_ + ucol];
            Us[bk][nl]     = uv.x;
            Us[bk][nl + 1] = uv.y;
            __syncthreads();
#pragma unroll
            for (int kk = 0; kk < 16; kk++) {
                float4 ra = *(const float4*)&As[kk][ty * 4];
                float2 rb = *(const float2*)&Us[kk][tx * 2];
                acc00 += ra.x * rb.x; acc01 += ra.x * rb.y;
                acc10 += ra.y * rb.x; acc11 += ra.y * rb.y;
                acc20 += ra.z * rb.x; acc21 += ra.z * rb.y;
                acc30 += ra.w * rb.x; acc31 += ra.w * rb.y;
            }
            __syncthreads();
        }

        Gs[ty * 4 + 0][tx * 2] = acc00; Gs[ty * 4 + 0][tx * 2 + 1] = acc01;
        Gs[ty * 4 + 1][tx * 2] = acc10; Gs[ty * 4 + 1][tx * 2 + 1] = acc11;
        Gs[ty * 4 + 2][tx * 2] = acc20; Gs[ty * 4 + 2][tx * 2 + 1] = acc21;
        Gs[ty * 4 + 3][tx * 2] = acc30; Gs[ty * 4 + 3][tx * 2 + 1] = acc31;
        __syncthreads();

        // fused cell update: 64 b x 8 j = 512 elems, 2 per thread
#pragma unroll
        for (int e = tid; e < 512; e += 256) {
            int b = e >> 3;
            int jj = e & 7;
            int j = j0 + jj;
            const float* xw = &g_xw[((size_t)t * B_ + b) * G_];
            float vi = xw[j]          + Gs[b][jj];
            float vf = xw[H_ + j]     + Gs[b][8 + jj];
            float vg = xw[2 * H_ + j] + Gs[b][16 + jj];
            float vo = xw[3 * H_ + j] + Gs[b][24 + jj];

            float ig = 1.f / (1.f + expf(-vi));
            float fg = 1.f / (1.f + expf(-vf));
            float gg = tanhf(vg);
            float og = 1.f / (1.f + expf(-vo));

            int sidx = b * H_ + j;
            float c = fg * g_c[sidx] + ig * gg;
            float hv = og * tanhf(c);
            g_c[sidx] = c;
            hnext[sidx] = hv;
            out[(size_t)b * ((size_t)S_ * H_) + (size_t)t * H_ + j] = hv;
            if (t == S_ - 1 && cT != nullptr) {
                hT[sidx] = hv;
                cT[sidx] = c;
            }
        }

        // ---- grid barrier: all new-h writes visible before next step's reads ----
        __syncthreads();
        if (tid == 0) {
            __threadfence();
            unsigned arr = atomicAdd(&g_count, 1);
            if (arr == NBLK - 1) {
                atomicExch(&g_count, 0);
                __threadfence();
                atomicAdd(&g_gen, 1);
            } else {
                while (*(volatile unsigned*)&g_gen <= gen) {
                    __nanosleep(64);
                }
            }
            __threadfence();
        }
        gen++;
        __syncthreads();
    }
}

extern "C" void kernel_launch(void* const* d_in, const int* in_sizes, int n_in,
                              void* d_out, int out_size) {
    const float* x    = (const float*)d_in[0];
    const float* W    = (const float*)d_in[1];
    const float* U    = (const float*)d_in[2];
    const float* bias = (const float*)d_in[3];
    float* out = (float*)d_out;

    // Output may be hidden_seq only, or hidden_seq + h_T + c_T.
    float* hT = nullptr;
    float* cT = nullptr;
    long long need = (long long)B_ * S_ * H_ + 2LL * B_ * H_;
    if ((long long)out_size >= need) {
        hT = out + (size_t)B_ * S_ * H_;
        cT = hT + (size_t)B_ * H_;
    }

    init_state<<<(B_ * H_) / 256, 256>>>();
    gemm_xw<<<dim3(G_ / 128, (B_ * S_) / 128), 256>>>(x, W, bias);
    lstm_recur<<<NBLK, 256>>>(U, out, hT, cT);
}

// round 5
// speedup vs baseline: 1.7007x; 1.7007x over previous
#include <cuda_runtime.h>
#include <cuda_bf16.h>
#include <cstdint>
#include <cmath>

#define B_ 64
#define S_ 512
#define D_ 1024
#define H_ 1024
#define G_ 4096
#define NBLK 128

// ---------------- scratch (device globals) ----------------
__device__ float g_xw[(size_t)S_ * G_ * B_];          // [t][n'(perm)][b] fp32
__device__ __nv_bfloat16 g_xh[(size_t)B_ * S_ * D_];  // x hi
__device__ __nv_bfloat16 g_xl[(size_t)B_ * S_ * D_];  // x lo
__device__ __nv_bfloat16 g_Wh[(size_t)G_ * D_];       // W^T perm [n'][k] hi
__device__ __nv_bfloat16 g_Wl[(size_t)G_ * D_];
__device__ __nv_bfloat16 g_Uh[(size_t)G_ * H_];       // U^T perm [n'][k] hi
__device__ __nv_bfloat16 g_Ul[(size_t)G_ * H_];
__device__ __nv_bfloat16 g_hh[2][B_ * H_];            // h hi [b][j], dbl buf
__device__ __nv_bfloat16 g_hl[2][B_ * H_];            // h lo
__device__ float g_c[H_ * B_];                        // c  [j][b]
__device__ unsigned g_count, g_gen;

// ---------------- helpers ----------------
__device__ __forceinline__ uint32_t smem_u32(const void* p) {
    uint32_t a;
    asm("{ .reg .u64 t; cvta.to.shared.u64 t, %1; cvt.u32.u64 %0, t; }" : "=r"(a) : "l"(p));
    return a;
}
__device__ __forceinline__ void ldm_x4(uint32_t* r, uint32_t a) {
    asm volatile("ldmatrix.sync.aligned.m8n8.x4.shared.b16 {%0,%1,%2,%3}, [%4];"
                 : "=r"(r[0]), "=r"(r[1]), "=r"(r[2]), "=r"(r[3]) : "r"(a));
}
__device__ __forceinline__ void ldm_x2(uint32_t* r, uint32_t a) {
    asm volatile("ldmatrix.sync.aligned.m8n8.x2.shared.b16 {%0,%1}, [%2];"
                 : "=r"(r[0]), "=r"(r[1]) : "r"(a));
}
__device__ __forceinline__ void mma16816(float* d, const uint32_t* a, const uint32_t* b) {
    asm volatile("mma.sync.aligned.m16n8k16.row.col.f32.bf16.bf16.f32 "
                 "{%0,%1,%2,%3},{%4,%5,%6,%7},{%8,%9},{%0,%1,%2,%3};"
                 : "+f"(d[0]), "+f"(d[1]), "+f"(d[2]), "+f"(d[3])
                 : "r"(a[0]), "r"(a[1]), "r"(a[2]), "r"(a[3]), "r"(b[0]), "r"(b[1]));
}

// ---------------- init ----------------
__global__ void init_state() {
    int i = blockIdx.x * 256 + threadIdx.x;   // 0..65535
    __nv_bfloat16 z = __float2bfloat16(0.f);
    g_hh[0][i] = z; g_hh[1][i] = z;
    g_hl[0][i] = z; g_hl[1][i] = z;
    g_c[i] = 0.f;
    if (i == 0) { g_count = 0; g_gen = 0; }
}

// ---------------- split x into bf16 hi/lo ----------------
__global__ void split_x(const float* __restrict__ x) {
    size_t i = ((size_t)blockIdx.x * 256 + threadIdx.x) * 4;
    float4 v = *(const float4*)(x + i);
    __nv_bfloat16 h0 = __float2bfloat16(v.x), h1 = __float2bfloat16(v.y);
    __nv_bfloat16 h2 = __float2bfloat16(v.z), h3 = __float2bfloat16(v.w);
    __nv_bfloat16 hb[4] = {h0, h1, h2, h3};
    __nv_bfloat16 lb[4] = {__float2bfloat16(v.x - __bfloat162float(h0)),
                           __float2bfloat16(v.y - __bfloat162float(h1)),
                           __float2bfloat16(v.z - __bfloat162float(h2)),
                           __float2bfloat16(v.w - __bfloat162float(h3))};
    *(uint2*)(g_xh + i) = *(uint2*)hb;
    *(uint2*)(g_xl + i) = *(uint2*)lb;
}

// ---------------- W/U: transpose + gate-interleave perm + split ----------------
// in [k][n] (1024 x 4096). out[n'][k] bf16 hi/lo, n' = (j>>3)*32 + gate*8 + (j&7)
__global__ void prep_w(const float* __restrict__ in, int which) {
    __shared__ float tile[32][33];
    __nv_bfloat16* oh = which ? g_Uh : g_Wh;
    __nv_bfloat16* ol = which ? g_Ul : g_Wl;
    int n0 = blockIdx.x * 32, k0 = blockIdx.y * 32;
    int tx = threadIdx.x, ty = threadIdx.y;
#pragma unroll
    for (int i = 0; i < 4; i++)
        tile[ty + i * 8][tx] = in[(size_t)(k0 + ty + i * 8) * G_ + n0 + tx];
    __syncthreads();
#pragma unroll
    for (int i = 0; i < 4; i++) {
        int n = n0 + ty + i * 8;
        int gate = n >> 10, j = n & 1023;
        int np = ((j >> 3) << 5) + (gate << 3) + (j & 7);
        float v = tile[tx][ty + i * 8];
        __nv_bfloat16 h = __float2bfloat16(v);
        oh[(size_t)np * 1024 + k0 + tx] = h;
        ol[(size_t)np * 1024 + k0 + tx] = __float2bfloat16(v - __bfloat162float(h));
    }
}

// ---------------- xW GEMM (mma.sync bf16x3): g_xw[t][n'][b] = x@W + bias ----------------
#define XP 80                 // smem row pitch bytes (32 bf16 + pad)
#define XB (128 * XP)         // 10240 per buffer
#define XAL (2 * XB)
#define XBH (4 * XB)
#define XBL (6 * XB)
#define XSM (8 * XB)          // 81920

__global__ __launch_bounds__(256, 1) void gemm_xw_tc(const float* __restrict__ bias) {
    extern __shared__ char sm[];
    uint32_t sb = smem_u32(sm);
    int tid = threadIdx.x, w = tid >> 5, lane = tid & 31;
    int wm = w & 1, wn = w >> 1;              // warp grid 2m x 4n, warp tile 64x32
    int n0 = blockIdx.x * 128, m0 = blockIdx.y * 128;

    // global staging: r = row 0..127, sel = which 32B half of the 64B k-chunk
    int r = tid & 127, sel = tid >> 7;
    int mg = m0 + r, bb = mg & 63, tt = mg >> 6;
    const __nv_bfloat16* pAh = g_xh + ((size_t)bb * S_ + tt) * D_ + sel * 16;
    const __nv_bfloat16* pAl = g_xl + ((size_t)bb * S_ + tt) * D_ + sel * 16;
    const __nv_bfloat16* pBh = g_Wh + (size_t)(n0 + r) * D_ + sel * 16;
    const __nv_bfloat16* pBl = g_Wl + (size_t)(n0 + r) * D_ + sel * 16;
    uint32_t stOff = (uint32_t)(r * XP + sel * 32);

    uint32_t aoff = (uint32_t)((wm * 64 + (lane & 15)) * XP + (lane >> 4) * 16);
    uint32_t boff = (uint32_t)((wn * 32 + (lane & 15)) * XP + (lane >> 4) * 16);

    float acc[4][4][4];
#pragma unroll
    for (int i = 0; i < 4; i++)
#pragma unroll
        for (int j = 0; j < 4; j++)
#pragma unroll
            for (int q = 0; q < 4; q++) acc[i][j][q] = 0.f;

    uint4 vah[2], val[2], vbh[2], vbl[2];
#pragma unroll
    for (int i = 0; i < 2; i++) {
        vah[i] = *(const uint4*)(pAh + i * 8);
        val[i] = *(const uint4*)(pAl + i * 8);
        vbh[i] = *(const uint4*)(pBh + i * 8);
        vbl[i] = *(const uint4*)(pBl + i * 8);
    }
#pragma unroll
    for (int i = 0; i < 2; i++) {
        *(uint4*)(sm + stOff + i * 16) = vah[i];
        *(uint4*)(sm + XAL + stOff + i * 16) = val[i];
        *(uint4*)(sm + XBH + stOff + i * 16) = vbh[i];
        *(uint4*)(sm + XBL + stOff + i * 16) = vbl[i];
    }

    for (int c = 0; c < 32; c++) {
        __syncthreads();
        if (c < 31) {
            int k0 = (c + 1) * 32;
#pragma unroll
            for (int i = 0; i < 2; i++) {
                vah[i] = *(const uint4*)(pAh + k0 + i * 8);
                val[i] = *(const uint4*)(pAl + k0 + i * 8);
                vbh[i] = *(const uint4*)(pBh + k0 + i * 8);
                vbl[i] = *(const uint4*)(pBl + k0 + i * 8);
            }
        }
        uint32_t buf = (uint32_t)(c & 1) * XB;
        uint32_t AH = sb + buf, AL = sb + XAL + buf;
        uint32_t BH = sb + XBH + buf, BL = sb + XBL + buf;
#pragma unroll
        for (int kk = 0; kk < 2; kk++) {
            uint32_t kb = kk * 32;
            uint32_t ah[4][4], al[4][4], bh[4][2], bl[4][2], tb[4];
#pragma unroll
            for (int mt = 0; mt < 4; mt++) {
                ldm_x4(ah[mt], AH + aoff + mt * 16 * XP + kb);
                ldm_x4(al[mt], AL + aoff + mt * 16 * XP + kb);
            }
#pragma unroll
            for (int g2 = 0; g2 < 2; g2++) {
                ldm_x4(tb, BH + boff + g2 * 16 * XP + kb);
                bh[g2 * 2][0] = tb[0]; bh[g2 * 2][1] = tb[2];
                bh[g2 * 2 + 1][0] = tb[1]; bh[g2 * 2 + 1][1] = tb[3];
                ldm_x4(tb, BL + boff + g2 * 16 * XP + kb);
                bl[g2 * 2][0] = tb[0]; bl[g2 * 2][1] = tb[2];
                bl[g2 * 2 + 1][0] = tb[1]; bl[g2 * 2 + 1][1] = tb[3];
            }
#pragma unroll
            for (int mt = 0; mt < 4; mt++)
#pragma unroll
                for (int nt = 0; nt < 4; nt++) {
                    mma16816(acc[mt][nt], ah[mt], bh[nt]);
                    mma16816(acc[mt][nt], ah[mt], bl[nt]);
                    mma16816(acc[mt][nt], al[mt], bh[nt]);
                }
        }
        if (c < 31) {
            uint32_t bn = (uint32_t)((c + 1) & 1) * XB;
#pragma unroll
            for (int i = 0; i < 2; i++) {
                *(uint4*)(sm + bn + stOff + i * 16) = vah[i];
                *(uint4*)(sm + XAL + bn + stOff + i * 16) = val[i];
                *(uint4*)(sm + XBH + bn + stOff + i * 16) = vbh[i];
                *(uint4*)(sm + XBL + bn + stOff + i * 16) = vbl[i];
            }
        }
    }

    // epilogue: stage [n_rel 0..127][m 0..127] fp32 pitch 132, then coalesced write
    __syncthreads();
    float* stg = (float*)sm;
#pragma unroll
    for (int mt = 0; mt < 4; mt++)
#pragma unroll
        for (int nt = 0; nt < 4; nt++) {
            int m = wm * 64 + mt * 16 + (lane >> 2);
            int nr = wn * 32 + nt * 8 + (lane & 3) * 2;
            stg[nr * 132 + m] = acc[mt][nt][0];
            stg[(nr + 1) * 132 + m] = acc[mt][nt][1];
            stg[nr * 132 + m + 8] = acc[mt][nt][2];
            stg[(nr + 1) * 132 + m + 8] = acc[mt][nt][3];
        }
    __syncthreads();
    int t0 = m0 >> 6;
#pragma unroll
    for (int i = 0; i < 16; i++) {
        int idx = tid + i * 256;
        int nr = idx >> 5, q = idx & 31;
        int np = n0 + nr;
        int gate = (np >> 3) & 3;
        int jo = ((np >> 5) << 3) + (np & 7);
        float bv = __ldg(bias + gate * H_ + jo);
        float4 v = *(float4*)&stg[nr * 132 + q * 4];
        v.x += bv; v.y += bv; v.z += bv; v.w += bv;
        *(float4*)&g_xw[((size_t)(t0 + (q >> 4)) * G_ + np) * 64 + (q & 15) * 4] = v;
    }
}

// ---------------- persistent recurrence (mma.sync bf16x3, U resident) ----------------
#define UPB 2064
#define HPB 272
#define RUL 66048
#define RH  132096
#define HB  17408
#define RHL (RH + 2 * HB)
#define RSM (RHL + 2 * HB)    // 201728

__global__ __launch_bounds__(256, 1) void lstm_recur(float* __restrict__ out,
                                                     float* __restrict__ hT,
                                                     float* __restrict__ cT) {
    extern __shared__ char sm[];
    uint32_t sb = smem_u32(sm);
    int tid = threadIdx.x, w = tid >> 5, lane = tid & 31;
    int wm = w & 1, wn = w >> 1;              // warp tile 32m x 8n
    int jt = blockIdx.x, n0r = jt * 32, j0 = jt * 8;

    // preload resident U tile: 32 n' rows x 1024 k, hi+lo
    {
        int row = tid >> 3, kb = (tid & 7) * 128;
        const __nv_bfloat16* ph = g_Uh + (size_t)(n0r + row) * H_ + kb;
        const __nv_bfloat16* pl = g_Ul + (size_t)(n0r + row) * H_ + kb;
        char* dh = sm + row * UPB + kb * 2;
        char* dl = sm + RUL + row * UPB + kb * 2;
#pragma unroll
        for (int i = 0; i < 16; i++) {
            *(uint4*)(dh + i * 16) = *(const uint4*)(ph + i * 8);
            *(uint4*)(dl + i * 16) = *(const uint4*)(pl + i * 8);
        }
    }
    int rr = tid >> 2, kq = (tid & 3) * 32;
    uint32_t hst = (uint32_t)(rr * HPB + kq * 2);
    uint32_t aoff = (uint32_t)((wm * 32 + (lane & 15)) * HPB + (lane >> 4) * 16);
    uint32_t uoff = (uint32_t)((wn * 8 + (lane & 7)) * UPB + ((lane >> 3) & 1) * 16);
    __syncthreads();

    unsigned gen = 0;
    for (int t = 0; t < S_; t++) {
        const __nv_bfloat16* hh = g_hh[t & 1];
        const __nv_bfloat16* hl = g_hl[t & 1];
        float acc0[4] = {0.f, 0.f, 0.f, 0.f};
        float acc1[4] = {0.f, 0.f, 0.f, 0.f};

        uint4 rh[4], rl[4];
        {
            size_t gb = (size_t)rr * H_ + kq;
#pragma unroll
            for (int i = 0; i < 4; i++) {
                rh[i] = __ldcg((const uint4*)(hh + gb + i * 8));
                rl[i] = __ldcg((const uint4*)(hl + gb + i * 8));
            }
#pragma unroll
            for (int i = 0; i < 4; i++) {
                *(uint4*)(sm + RH + hst + i * 16) = rh[i];
                *(uint4*)(sm + RHL + hst + i * 16) = rl[i];
            }
        }
        for (int c = 0; c < 8; c++) {
            __syncthreads();
            if (c < 7) {
                size_t gb = (size_t)rr * H_ + (size_t)(c + 1) * 128 + kq;
#pragma unroll
                for (int i = 0; i < 4; i++) {
                    rh[i] = __ldcg((const uint4*)(hh + gb + i * 8));
                    rl[i] = __ldcg((const uint4*)(hl + gb + i * 8));
                }
            }
            uint32_t AH = sb + RH + (uint32_t)(c & 1) * HB;
            uint32_t AL = sb + RHL + (uint32_t)(c & 1) * HB;
            uint32_t ub = sb + uoff + (uint32_t)c * 256;
#pragma unroll
            for (int kk = 0; kk < 8; kk++) {
                uint32_t kb = kk * 32;
                uint32_t ah0[4], ah1[4], al0[4], al1[4], bh[2], bl[2];
                ldm_x4(ah0, AH + aoff + kb);
                ldm_x4(ah1, AH + aoff + 16 * HPB + kb);
                ldm_x4(al0, AL + aoff + kb);
                ldm_x4(al1, AL + aoff + 16 * HPB + kb);
                ldm_x2(bh, ub + kb);
                ldm_x2(bl, ub + RUL + kb);
                mma16816(acc0, ah0, bh);
                mma16816(acc0, ah0, bl);
                mma16816(acc0, al0, bh);
                mma16816(acc1, ah1, bh);
                mma16816(acc1, ah1, bl);
                mma16816(acc1, al1, bh);
            }
            if (c < 7) {
                uint32_t o = (uint32_t)((c + 1) & 1) * HB;
#pragma unroll
                for (int i = 0; i < 4; i++) {
                    *(uint4*)(sm + RH + o + hst + i * 16) = rh[i];
                    *(uint4*)(sm + RHL + o + hst + i * 16) = rl[i];
                }
            }
        }
        __syncthreads();
        // stage gates Gs[64 b][33] fp32 (overlay on A buf0, dead now)
        float* Gs = (float*)(sm + RH);
        {
            int bb = wm * 32 + (lane >> 2);
            int npb = wn * 8 + (lane & 3) * 2;
            Gs[bb * 33 + npb] = acc0[0];       Gs[bb * 33 + npb + 1] = acc0[1];
            Gs[(bb + 8) * 33 + npb] = acc0[2]; Gs[(bb + 8) * 33 + npb + 1] = acc0[3];
            Gs[(bb + 16) * 33 + npb] = acc1[0];       Gs[(bb + 16) * 33 + npb + 1] = acc1[1];
            Gs[(bb + 24) * 33 + npb] = acc1[2];       Gs[(bb + 24) * 33 + npb + 1] = acc1[3];
        }
        __syncthreads();
        if (tid < 64) {
            int b = tid;
            const float* xwrow = g_xw + ((size_t)t * G_ + n0r) * 64;
            float hv8[8], cc8[8];
#pragma unroll
            for (int jj = 0; jj < 8; jj++) {
                float vi = Gs[b * 33 + jj]      + xwrow[(size_t)jj * 64 + b];
                float vf = Gs[b * 33 + 8 + jj]  + xwrow[(size_t)(8 + jj) * 64 + b];
                float vg = Gs[b * 33 + 16 + jj] + xwrow[(size_t)(16 + jj) * 64 + b];
                float vo = Gs[b * 33 + 24 + jj] + xwrow[(size_t)(24 + jj) * 64 + b];
                float ig = 1.f / (1.f + expf(-vi));
                float fg = 1.f / (1.f + expf(-vf));
                float gg = tanhf(vg);
                float og = 1.f / (1.f + expf(-vo));
                int ci = (j0 + jj) * 64 + b;
                float cc = fg * g_c[ci] + ig * gg;
                float hv = og * tanhf(cc);
                g_c[ci] = cc;
                hv8[jj] = hv;
                cc8[jj] = cc;
            }
            __nv_bfloat16 hb[8], lb[8];
#pragma unroll
            for (int jj = 0; jj < 8; jj++) {
                hb[jj] = __float2bfloat16(hv8[jj]);
                lb[jj] = __float2bfloat16(hv8[jj] - __bfloat162float(hb[jj]));
            }
            *(uint4*)&g_hh[(t + 1) & 1][b * H_ + j0] = *(uint4*)hb;
            *(uint4*)&g_hl[(t + 1) & 1][b * H_ + j0] = *(uint4*)lb;
            float* op = out + (size_t)b * ((size_t)S_ * H_) + (size_t)t * H_ + j0;
            *(float4*)op = make_float4(hv8[0], hv8[1], hv8[2], hv8[3]);
            *(float4*)(op + 4) = make_float4(hv8[4], hv8[5], hv8[6], hv8[7]);
            if (t == S_ - 1 && cT != nullptr) {
#pragma unroll
                for (int jj = 0; jj < 8; jj++) {
                    hT[b * H_ + j0 + jj] = hv8[jj];
                    cT[b * H_ + j0 + jj] = cc8[jj];
                }
            }
        }
        // grid barrier (proven R2 pattern)
        __syncthreads();
        if (tid == 0) {
            __threadfence();
            unsigned arr = atomicAdd(&g_count, 1);
            if (arr == NBLK - 1) {
                atomicExch(&g_count, 0);
                __threadfence();
                atomicAdd(&g_gen, 1);
            } else {
                while (*(volatile unsigned*)&g_gen <= gen) { __nanosleep(64); }
            }
            __threadfence();
        }
        gen++;
        __syncthreads();
    }
}

// ---------------- launch ----------------
extern "C" void kernel_launch(void* const* d_in, const int* in_sizes, int n_in,
                              void* d_out, int out_size) {
    const float* x    = (const float*)d_in[0];
    const float* W    = (const float*)d_in[1];
    const float* U    = (const float*)d_in[2];
    const float* bias = (const float*)d_in[3];
    float* out = (float*)d_out;

    float* hT = nullptr;
    float* cT = nullptr;
    long long need = (long long)B_ * S_ * H_ + 2LL * B_ * H_;
    if ((long long)out_size >= need) {
        hT = out + (size_t)B_ * S_ * H_;
        cT = hT + (size_t)B_ * H_;
    }

    cudaFuncSetAttribute(gemm_xw_tc, cudaFuncAttributeMaxDynamicSharedMemorySize, XSM);
    cudaFuncSetAttribute(lstm_recur, cudaFuncAttributeMaxDynamicSharedMemorySize, RSM);

    init_state<<<256, 256>>>();
    split_x<<<(B_ * S_ * D_) / 1024, 256>>>(x);
    prep_w<<<dim3(128, 32), dim3(32, 8)>>>(W, 0);
    prep_w<<<dim3(128, 32), dim3(32, 8)>>>(U, 1);
    gemm_xw_tc<<<dim3(32, 256), 256, XSM>>>(bias);
    lstm_recur<<<NBLK, 256, RSM>>>(out, hT, cT);
}

// round 6
// speedup vs baseline: 3.0622x; 1.8006x over previous
#include <cuda_runtime.h>
#include <cuda_fp16.h>
#include <cstdint>
#include <cmath>

#define B_ 64
#define S_ 512
#define D_ 1024
#define H_ 1024
#define G_ 4096
#define NBLK 128

// ---------------- scratch (device globals) ----------------
__device__ float g_xw[(size_t)S_ * G_ * B_];    // [t][n'(perm)][b] fp32
__device__ __half g_xh[(size_t)B_ * S_ * D_];   // x fp16 (rounded)
__device__ __half g_Wh[(size_t)G_ * D_];        // W^T perm [n'][k] hi
__device__ __half g_Wl[(size_t)G_ * D_];        // W^T perm lo
__device__ __half g_Uh[(size_t)G_ * H_];        // U^T perm hi
__device__ __half g_Ul[(size_t)G_ * H_];        // U^T perm lo
__device__ __half g_hh[2][B_ * H_];             // h fp16 [b][j], dbl buf
__device__ float g_c[H_ * B_];                  // c [j][b]
__device__ unsigned g_count, g_gen;

// ---------------- helpers ----------------
__device__ __forceinline__ uint32_t smem_u32(const void* p) {
    uint32_t a;
    asm("{ .reg .u64 t; cvta.to.shared.u64 t, %1; cvt.u32.u64 %0, t; }" : "=r"(a) : "l"(p));
    return a;
}
__device__ __forceinline__ void ldm_x4(uint32_t* r, uint32_t a) {
    asm volatile("ldmatrix.sync.aligned.m8n8.x4.shared.b16 {%0,%1,%2,%3}, [%4];"
                 : "=r"(r[0]), "=r"(r[1]), "=r"(r[2]), "=r"(r[3]) : "r"(a));
}
__device__ __forceinline__ void ldm_x2(uint32_t* r, uint32_t a) {
    asm volatile("ldmatrix.sync.aligned.m8n8.x2.shared.b16 {%0,%1}, [%2];"
                 : "=r"(r[0]), "=r"(r[1]) : "r"(a));
}
__device__ __forceinline__ void mma16816(float* d, const uint32_t* a, const uint32_t* b) {
    asm volatile("mma.sync.aligned.m16n8k16.row.col.f32.f16.f16.f32 "
                 "{%0,%1,%2,%3},{%4,%5,%6,%7},{%8,%9},{%0,%1,%2,%3};"
                 : "+f"(d[0]), "+f"(d[1]), "+f"(d[2]), "+f"(d[3])
                 : "r"(a[0]), "r"(a[1]), "r"(a[2]), "r"(a[3]), "r"(b[0]), "r"(b[1]));
}

// ---------------- init: barrier vars only (h/c never read before written) ----------------
__global__ void init_state() {
    if (threadIdx.x == 0) { g_count = 0; g_gen = 0; }
}

// ---------------- x: fp32 -> fp16 ----------------
__global__ void split_x(const float* __restrict__ x) {
    size_t i = ((size_t)blockIdx.x * 256 + threadIdx.x) * 8;
    float4 v0 = *(const float4*)(x + i);
    float4 v1 = *(const float4*)(x + i + 4);
    __half h[8] = {__float2half(v0.x), __float2half(v0.y), __float2half(v0.z), __float2half(v0.w),
                   __float2half(v1.x), __float2half(v1.y), __float2half(v1.z), __float2half(v1.w)};
    *(uint4*)(g_xh + i) = *(uint4*)h;
}

// ---------------- W/U: transpose + gate-interleave perm + fp16 hi/lo split ----------------
// in [k][n] (1024 x 4096). out[n'][k], n' = (j>>3)*32 + gate*8 + (j&7)
__global__ void prep_w(const float* __restrict__ in, int which) {
    __shared__ float tile[32][33];
    __half* oh = which ? g_Uh : g_Wh;
    __half* ol = which ? g_Ul : g_Wl;
    int n0 = blockIdx.x * 32, k0 = blockIdx.y * 32;
    int tx = threadIdx.x, ty = threadIdx.y;
#pragma unroll
    for (int i = 0; i < 4; i++)
        tile[ty + i * 8][tx] = in[(size_t)(k0 + ty + i * 8) * G_ + n0 + tx];
    __syncthreads();
#pragma unroll
    for (int i = 0; i < 4; i++) {
        int n = n0 + ty + i * 8;
        int gate = n >> 10, j = n & 1023;
        int np = ((j >> 3) << 5) + (gate << 3) + (j & 7);
        float v = tile[tx][ty + i * 8];
        __half h = __float2half(v);
        oh[(size_t)np * 1024 + k0 + tx] = h;
        ol[(size_t)np * 1024 + k0 + tx] = __float2half(v - __half2float(h));
    }
}

// ---------------- xW GEMM (mma.sync fp16 2-term): g_xw[t][n'][b] = x@(Wh+Wl) + bias ----------------
#define XP 80                 // smem row pitch bytes (32 fp16 + pad)
#define XB (128 * XP)         // 10240 per buffer
#define XBH (2 * XB)
#define XBL (4 * XB)
#define XSM 67584             // >= 6*XB and >= 128*132*4 epilogue staging

__global__ __launch_bounds__(256, 2) void gemm_xw_tc(const float* __restrict__ bias) {
    extern __shared__ char sm[];
    uint32_t sb = smem_u32(sm);
    int tid = threadIdx.x, w = tid >> 5, lane = tid & 31;
    int wm = w & 1, wn = w >> 1;              // warp grid 2m x 4n, warp tile 64x32
    int n0 = blockIdx.x * 128, m0 = blockIdx.y * 128;

    int r = tid & 127, sel = tid >> 7;        // staging: row, 32B half
    int mg = m0 + r, bb = mg & 63, tt = mg >> 6;
    const __half* pA  = g_xh + ((size_t)bb * S_ + tt) * D_ + sel * 16;
    const __half* pBh = g_Wh + (size_t)(n0 + r) * D_ + sel * 16;
    const __half* pBl = g_Wl + (size_t)(n0 + r) * D_ + sel * 16;
    uint32_t stOff = (uint32_t)(r * XP + sel * 32);

    uint32_t aoff = (uint32_t)((wm * 64 + (lane & 15)) * XP + (lane >> 4) * 16);
    uint32_t boff = (uint32_t)((wn * 32 + (lane & 15)) * XP + (lane >> 4) * 16);

    float acc[4][4][4];
#pragma unroll
    for (int i = 0; i < 4; i++)
#pragma unroll
        for (int j = 0; j < 4; j++)
#pragma unroll
            for (int q = 0; q < 4; q++) acc[i][j][q] = 0.f;

    uint4 va[2], vbh[2], vbl[2];
#pragma unroll
    for (int i = 0; i < 2; i++) {
        va[i]  = *(const uint4*)(pA + i * 8);
        vbh[i] = *(const uint4*)(pBh + i * 8);
        vbl[i] = *(const uint4*)(pBl + i * 8);
    }
#pragma unroll
    for (int i = 0; i < 2; i++) {
        *(uint4*)(sm + stOff + i * 16) = va[i];
        *(uint4*)(sm + XBH + stOff + i * 16) = vbh[i];
        *(uint4*)(sm + XBL + stOff + i * 16) = vbl[i];
    }

    for (int c = 0; c < 32; c++) {
        __syncthreads();
        if (c < 31) {
            int k0 = (c + 1) * 32;
#pragma unroll
            for (int i = 0; i < 2; i++) {
                va[i]  = *(const uint4*)(pA + k0 + i * 8);
                vbh[i] = *(const uint4*)(pBh + k0 + i * 8);
                vbl[i] = *(const uint4*)(pBl + k0 + i * 8);
            }
        }
        uint32_t buf = (uint32_t)(c & 1) * XB;
        uint32_t AH = sb + buf, BH = sb + XBH + buf, BL = sb + XBL + buf;
#pragma unroll
        for (int kk = 0; kk < 2; kk++) {
            uint32_t kb = kk * 32;
            uint32_t ah[4][4], bh[4][2], bl[4][2], tb[4];
#pragma unroll
            for (int mt = 0; mt < 4; mt++)
                ldm_x4(ah[mt], AH + aoff + mt * 16 * XP + kb);
#pragma unroll
            for (int g2 = 0; g2 < 2; g2++) {
                ldm_x4(tb, BH + boff + g2 * 16 * XP + kb);
                bh[g2 * 2][0] = tb[0]; bh[g2 * 2][1] = tb[2];
                bh[g2 * 2 + 1][0] = tb[1]; bh[g2 * 2 + 1][1] = tb[3];
                ldm_x4(tb, BL + boff + g2 * 16 * XP + kb);
                bl[g2 * 2][0] = tb[0]; bl[g2 * 2][1] = tb[2];
                bl[g2 * 2 + 1][0] = tb[1]; bl[g2 * 2 + 1][1] = tb[3];
            }
#pragma unroll
            for (int mt = 0; mt < 4; mt++)
#pragma unroll
                for (int nt = 0; nt < 4; nt++) {
                    mma16816(acc[mt][nt], ah[mt], bh[nt]);
                    mma16816(acc[mt][nt], ah[mt], bl[nt]);
                }
        }
        if (c < 31) {
            uint32_t bn = (uint32_t)((c + 1) & 1) * XB;
#pragma unroll
            for (int i = 0; i < 2; i++) {
                *(uint4*)(sm + bn + stOff + i * 16) = va[i];
                *(uint4*)(sm + XBH + bn + stOff + i * 16) = vbh[i];
                *(uint4*)(sm + XBL + bn + stOff + i * 16) = vbl[i];
            }
        }
    }

    // epilogue: stage [n_rel][m] fp32 pitch 132, then coalesced write
    __syncthreads();
    float* stg = (float*)sm;
#pragma unroll
    for (int mt = 0; mt < 4; mt++)
#pragma unroll
        for (int nt = 0; nt < 4; nt++) {
            int m = wm * 64 + mt * 16 + (lane >> 2);
            int nr = wn * 32 + nt * 8 + (lane & 3) * 2;
            stg[nr * 132 + m] = acc[mt][nt][0];
            stg[(nr + 1) * 132 + m] = acc[mt][nt][1];
            stg[nr * 132 + m + 8] = acc[mt][nt][2];
            stg[(nr + 1) * 132 + m + 8] = acc[mt][nt][3];
        }
    __syncthreads();
    int t0 = m0 >> 6;
#pragma unroll
    for (int i = 0; i < 16; i++) {
        int idx = tid + i * 256;
        int nr = idx >> 5, q = idx & 31;
        int np = n0 + nr;
        int gate = (np >> 3) & 3;
        int jo = ((np >> 5) << 3) + (np & 7);
        float bv = __ldg(bias + gate * H_ + jo);
        float4 v = *(float4*)&stg[nr * 132 + q * 4];
        v.x += bv; v.y += bv; v.z += bv; v.w += bv;
        *(float4*)&g_xw[((size_t)(t0 + (q >> 4)) * G_ + np) * 64 + (q & 15) * 4] = v;
    }
}

// ---------------- persistent recurrence (fp16 2-term, U hi+lo resident) ----------------
#define UPB 2064
#define HPB 272
#define RUL 66048             // U lo region
#define RH  132096            // h dbl buffers
#define HB  17408
#define RXW (RH + 2 * HB)     // 166912: xw[t] tile staging (8192B)
#define RSM (RXW + 8192)      // 175104

__global__ __launch_bounds__(256, 1) void lstm_recur(float* __restrict__ out,
                                                     float* __restrict__ hT,
                                                     float* __restrict__ cT) {
    extern __shared__ char sm[];
    uint32_t sb = smem_u32(sm);
    int tid = threadIdx.x, w = tid >> 5, lane = tid & 31;
    int wm = w & 1, wn = w >> 1;              // warp tile 32m x 8n
    int jt = blockIdx.x, n0r = jt * 32, j0 = jt * 8;

    // preload resident U tile: 32 n' rows x 1024 k, hi + lo
    {
        int row = tid >> 3, kb = (tid & 7) * 128;
        const __half* ph = g_Uh + (size_t)(n0r + row) * H_ + kb;
        const __half* pl = g_Ul + (size_t)(n0r + row) * H_ + kb;
        char* dh = sm + row * UPB + kb * 2;
        char* dl = sm + RUL + row * UPB + kb * 2;
#pragma unroll
        for (int i = 0; i < 16; i++) {
            *(uint4*)(dh + i * 16) = *(const uint4*)(ph + i * 8);
            *(uint4*)(dl + i * 16) = *(const uint4*)(pl + i * 8);
        }
    }
    int rr = tid >> 2, kq = (tid & 3) * 32;
    uint32_t hst = (uint32_t)(rr * HPB + kq * 2);
    uint32_t aoff = (uint32_t)((wm * 32 + (lane & 15)) * HPB + (lane >> 4) * 16);
    uint32_t uoff = (uint32_t)((wn * 8 + (lane & 7)) * UPB + ((lane >> 3) & 1) * 16);
    float* XWS = (float*)(sm + RXW);
    __syncthreads();

    unsigned gen = 0;
    for (int t = 0; t < S_; t++) {
        // stage xw[t] tile (2048 fp32) early — overlaps with GEMM below
        {
            const float* xwp = g_xw + ((size_t)t * G_ + n0r) * 64 + tid * 8;
            float4 v0 = __ldcg((const float4*)xwp);
            float4 v1 = __ldcg((const float4*)(xwp + 4));
            ((float4*)XWS)[tid * 2] = v0;
            ((float4*)XWS)[tid * 2 + 1] = v1;
        }

        float acc0[4] = {0.f, 0.f, 0.f, 0.f};
        float acc1[4] = {0.f, 0.f, 0.f, 0.f};

        if (t > 0) {
            const __half* hh = g_hh[t & 1];
            uint4 rh[4];
            {
                size_t gb = (size_t)rr * H_ + kq;
#pragma unroll
                for (int i = 0; i < 4; i++)
                    rh[i] = __ldcg((const uint4*)(hh + gb + i * 8));
#pragma unroll
                for (int i = 0; i < 4; i++)
                    *(uint4*)(sm + RH + hst + i * 16) = rh[i];
            }
            for (int c = 0; c < 8; c++) {
                __syncthreads();
                if (c < 7) {
                    size_t gb = (size_t)rr * H_ + (size_t)(c + 1) * 128 + kq;
#pragma unroll
                    for (int i = 0; i < 4; i++)
                        rh[i] = __ldcg((const uint4*)(hh + gb + i * 8));
                }
                uint32_t AH = sb + RH + (uint32_t)(c & 1) * HB;
                uint32_t ub = sb + uoff + (uint32_t)c * 256;
#pragma unroll
                for (int kk = 0; kk < 8; kk++) {
                    uint32_t kb = kk * 32;
                    uint32_t ah0[4], ah1[4], bh[2], bl[2];
                    ldm_x4(ah0, AH + aoff + kb);
                    ldm_x4(ah1, AH + aoff + 16 * HPB + kb);
                    ldm_x2(bh, ub + kb);
                    ldm_x2(bl, ub + RUL + kb);
                    mma16816(acc0, ah0, bh);
                    mma16816(acc0, ah0, bl);
                    mma16816(acc1, ah1, bh);
                    mma16816(acc1, ah1, bl);
                }
                if (c < 7) {
                    uint32_t o = (uint32_t)((c + 1) & 1) * HB;
#pragma unroll
                    for (int i = 0; i < 4; i++)
                        *(uint4*)(sm + RH + o + hst + i * 16) = rh[i];
                }
            }
        }
        __syncthreads();
        // stage gates Gs[64 b][33] fp32 (overlay on h buf0, dead now)
        float* Gs = (float*)(sm + RH);
        {
            int bb = wm * 32 + (lane >> 2);
            int npb = wn * 8 + (lane & 3) * 2;
            Gs[bb * 33 + npb] = acc0[0];        Gs[bb * 33 + npb + 1] = acc0[1];
            Gs[(bb + 8) * 33 + npb] = acc0[2];  Gs[(bb + 8) * 33 + npb + 1] = acc0[3];
            Gs[(bb + 16) * 33 + npb] = acc1[0]; Gs[(bb + 16) * 33 + npb + 1] = acc1[1];
            Gs[(bb + 24) * 33 + npb] = acc1[2]; Gs[(bb + 24) * 33 + npb + 1] = acc1[3];
        }
        __syncthreads();
        if (tid < 64) {
            int b = tid;
            float hv8[8], cc8[8];
#pragma unroll
            for (int jj = 0; jj < 8; jj++) {
                float vi = Gs[b * 33 + jj]      + XWS[jj * 64 + b];
                float vf = Gs[b * 33 + 8 + jj]  + XWS[(8 + jj) * 64 + b];
                float vg = Gs[b * 33 + 16 + jj] + XWS[(16 + jj) * 64 + b];
                float vo = Gs[b * 33 + 24 + jj] + XWS[(24 + jj) * 64 + b];
                float ig = 1.f / (1.f + expf(-vi));
                float fg = 1.f / (1.f + expf(-vf));
                float gg = tanhf(vg);
                float og = 1.f / (1.f + expf(-vo));
                int ci = (j0 + jj) * 64 + b;
                float cp = (t == 0) ? 0.f : g_c[ci];
                float cc = fg * cp + ig * gg;
                float hv = og * tanhf(cc);
                g_c[ci] = cc;
                hv8[jj] = hv;
                cc8[jj] = cc;
            }
            __half hb[8];
#pragma unroll
            for (int jj = 0; jj < 8; jj++) hb[jj] = __float2half(hv8[jj]);
            *(uint4*)&g_hh[(t + 1) & 1][b * H_ + j0] = *(uint4*)hb;
            float* op = out + (size_t)b * ((size_t)S_ * H_) + (size_t)t * H_ + j0;
            *(float4*)op = make_float4(hv8[0], hv8[1], hv8[2], hv8[3]);
            *(float4*)(op + 4) = make_float4(hv8[4], hv8[5], hv8[6], hv8[7]);
            if (t == S_ - 1 && cT != nullptr) {
#pragma unroll
                for (int jj = 0; jj < 8; jj++) {
                    hT[b * H_ + j0 + jj] = hv8[jj];
                    cT[b * H_ + j0 + jj] = cc8[jj];
                }
            }
        }
        // grid barrier (skip after last step)
        __syncthreads();
        if (t < S_ - 1) {
            if (tid == 0) {
                __threadfence();
                unsigned arr = atomicAdd(&g_count, 1);
                if (arr == NBLK - 1) {
                    atomicExch(&g_count, 0);
                    __threadfence();
                    atomicAdd(&g_gen, 1);
                } else {
                    while (*(volatile unsigned*)&g_gen <= gen) { __nanosleep(64); }
                }
                __threadfence();
            }
            gen++;
            __syncthreads();
        }
    }
}

// ---------------- launch ----------------
extern "C" void kernel_launch(void* const* d_in, const int* in_sizes, int n_in,
                              void* d_out, int out_size) {
    const float* x    = (const float*)d_in[0];
    const float* W    = (const float*)d_in[1];
    const float* U    = (const float*)d_in[2];
    const float* bias = (const float*)d_in[3];
    float* out = (float*)d_out;

    float* hT = nullptr;
    float* cT = nullptr;
    long long need = (long long)B_ * S_ * H_ + 2LL * B_ * H_;
    if ((long long)out_size >= need) {
        hT = out + (size_t)B_ * S_ * H_;
        cT = hT + (size_t)B_ * H_;
    }

    cudaFuncSetAttribute(gemm_xw_tc, cudaFuncAttributeMaxDynamicSharedMemorySize, XSM);
    cudaFuncSetAttribute(lstm_recur, cudaFuncAttributeMaxDynamicSharedMemorySize, RSM);

    init_state<<<1, 32>>>();
    split_x<<<(B_ * S_ * D_) / (256 * 8), 256>>>(x);
    prep_w<<<dim3(128, 32), dim3(32, 8)>>>(W, 0);
    prep_w<<<dim3(128, 32), dim3(32, 8)>>>(U, 1);
    gemm_xw_tc<<<dim3(32, 256), 256, XSM>>>(bias);
    lstm_recur<<<NBLK, 256, RSM>>>(out, hT, cT);
}

// round 7
// speedup vs baseline: 3.8530x; 1.2582x over previous
#include <cuda_runtime.h>
#include <cuda_fp16.h>
#include <cstdint>
#include <cmath>

#define B_ 64
#define S_ 512
#define D_ 1024
#define H_ 1024
#define G_ 4096
#define NBLK 128

// ---------------- scratch (device globals) ----------------
__device__ float g_xw[(size_t)S_ * G_ * B_];    // [t][n'(perm)][b] fp32
__device__ __half g_xh[(size_t)B_ * S_ * D_];   // x fp16
__device__ __half g_Wh[(size_t)G_ * D_];        // W^T perm [n'][k] fp16
__device__ __half g_Uh[(size_t)G_ * H_];        // U^T perm [n'][k] fp16
__device__ __half g_hh[2][B_ * H_];             // h fp16 [b][j], dbl buf
__device__ unsigned g_count, g_gen;

// ---------------- helpers ----------------
__device__ __forceinline__ uint32_t smem_u32(const void* p) {
    uint32_t a;
    asm("{ .reg .u64 t; cvta.to.shared.u64 t, %1; cvt.u32.u64 %0, t; }" : "=r"(a) : "l"(p));
    return a;
}
__device__ __forceinline__ void ldm_x4(uint32_t* r, uint32_t a) {
    asm volatile("ldmatrix.sync.aligned.m8n8.x4.shared.b16 {%0,%1,%2,%3}, [%4];"
                 : "=r"(r[0]), "=r"(r[1]), "=r"(r[2]), "=r"(r[3]) : "r"(a));
}
__device__ __forceinline__ void ldm_x2(uint32_t* r, uint32_t a) {
    asm volatile("ldmatrix.sync.aligned.m8n8.x2.shared.b16 {%0,%1}, [%2];"
                 : "=r"(r[0]), "=r"(r[1]) : "r"(a));
}
__device__ __forceinline__ void mma16816(float* d, const uint32_t* a, const uint32_t* b) {
    asm volatile("mma.sync.aligned.m16n8k16.row.col.f32.f16.f16.f32 "
                 "{%0,%1,%2,%3},{%4,%5,%6,%7},{%8,%9},{%0,%1,%2,%3};"
                 : "+f"(d[0]), "+f"(d[1]), "+f"(d[2]), "+f"(d[3])
                 : "r"(a[0]), "r"(a[1]), "r"(a[2]), "r"(a[3]), "r"(b[0]), "r"(b[1]));
}

// ---------------- init ----------------
__global__ void init_state() {
    if (threadIdx.x == 0) { g_count = 0; g_gen = 0; }
}

// ---------------- x: fp32 -> fp16 ----------------
__global__ void split_x(const float* __restrict__ x) {
    size_t i = ((size_t)blockIdx.x * 256 + threadIdx.x) * 8;
    float4 v0 = *(const float4*)(x + i);
    float4 v1 = *(const float4*)(x + i + 4);
    __half h[8] = {__float2half(v0.x), __float2half(v0.y), __float2half(v0.z), __float2half(v0.w),
                   __float2half(v1.x), __float2half(v1.y), __float2half(v1.z), __float2half(v1.w)};
    *(uint4*)(g_xh + i) = *(uint4*)h;
}

// ---------------- W/U: transpose + gate-interleave perm + fp16 ----------------
// in [k][n] (1024 x 4096). out[n'][k], n' = (j>>3)*32 + gate*8 + (j&7)
__global__ void prep_w(const float* __restrict__ in, int which) {
    __shared__ float tile[32][33];
    __half* oh = which ? g_Uh : g_Wh;
    int n0 = blockIdx.x * 32, k0 = blockIdx.y * 32;
    int tx = threadIdx.x, ty = threadIdx.y;
#pragma unroll
    for (int i = 0; i < 4; i++)
        tile[ty + i * 8][tx] = in[(size_t)(k0 + ty + i * 8) * G_ + n0 + tx];
    __syncthreads();
#pragma unroll
    for (int i = 0; i < 4; i++) {
        int n = n0 + ty + i * 8;
        int gate = n >> 10, j = n & 1023;
        int np = ((j >> 3) << 5) + (gate << 3) + (j & 7);
        oh[(size_t)np * 1024 + k0 + tx] = __float2half(tile[tx][ty + i * 8]);
    }
}

// ---------------- xW GEMM (mma.sync fp16): g_xw[t][n'][b] = x@W + bias ----------------
#define XP 80                 // smem row pitch bytes (32 fp16 + pad)
#define XB (128 * XP)         // 10240 per buffer
#define XBH (2 * XB)          // B buffers
#define XSM 67584             // >= 4*XB and >= 128*132*4 epilogue staging

__global__ __launch_bounds__(256, 2) void gemm_xw_tc(const float* __restrict__ bias) {
    extern __shared__ char sm[];
    uint32_t sb = smem_u32(sm);
    int tid = threadIdx.x, w = tid >> 5, lane = tid & 31;
    int wm = w & 1, wn = w >> 1;              // warp grid 2m x 4n, warp tile 64x32
    int n0 = blockIdx.x * 128, m0 = blockIdx.y * 128;

    int r = tid & 127, sel = tid >> 7;        // staging: row, 32B half
    int mg = m0 + r, bb = mg & 63, tt = mg >> 6;
    const __half* pA  = g_xh + ((size_t)bb * S_ + tt) * D_ + sel * 16;
    const __half* pBh = g_Wh + (size_t)(n0 + r) * D_ + sel * 16;
    uint32_t stOff = (uint32_t)(r * XP + sel * 32);

    uint32_t aoff = (uint32_t)((wm * 64 + (lane & 15)) * XP + (lane >> 4) * 16);
    uint32_t boff = (uint32_t)((wn * 32 + (lane & 15)) * XP + (lane >> 4) * 16);

    float acc[4][4][4];
#pragma unroll
    for (int i = 0; i < 4; i++)
#pragma unroll
        for (int j = 0; j < 4; j++)
#pragma unroll
            for (int q = 0; q < 4; q++) acc[i][j][q] = 0.f;

    uint4 va[2], vbh[2];
#pragma unroll
    for (int i = 0; i < 2; i++) {
        va[i]  = *(const uint4*)(pA + i * 8);
        vbh[i] = *(const uint4*)(pBh + i * 8);
    }
#pragma unroll
    for (int i = 0; i < 2; i++) {
        *(uint4*)(sm + stOff + i * 16) = va[i];
        *(uint4*)(sm + XBH + stOff + i * 16) = vbh[i];
    }

    for (int c = 0; c < 32; c++) {
        __syncthreads();
        if (c < 31) {
            int k0 = (c + 1) * 32;
#pragma unroll
            for (int i = 0; i < 2; i++) {
                va[i]  = *(const uint4*)(pA + k0 + i * 8);
                vbh[i] = *(const uint4*)(pBh + k0 + i * 8);
            }
        }
        uint32_t buf = (uint32_t)(c & 1) * XB;
        uint32_t AH = sb + buf, BH = sb + XBH + buf;
#pragma unroll
        for (int kk = 0; kk < 2; kk++) {
            uint32_t kb = kk * 32;
            uint32_t ah[4][4], bh[4][2], tb[4];
#pragma unroll
            for (int mt = 0; mt < 4; mt++)
                ldm_x4(ah[mt], AH + aoff + mt * 16 * XP + kb);
#pragma unroll
            for (int g2 = 0; g2 < 2; g2++) {
                ldm_x4(tb, BH + boff + g2 * 16 * XP + kb);
                bh[g2 * 2][0] = tb[0]; bh[g2 * 2][1] = tb[2];
                bh[g2 * 2 + 1][0] = tb[1]; bh[g2 * 2 + 1][1] = tb[3];
            }
#pragma unroll
            for (int mt = 0; mt < 4; mt++)
#pragma unroll
                for (int nt = 0; nt < 4; nt++)
                    mma16816(acc[mt][nt], ah[mt], bh[nt]);
        }
        if (c < 31) {
            uint32_t bn = (uint32_t)((c + 1) & 1) * XB;
#pragma unroll
            for (int i = 0; i < 2; i++) {
                *(uint4*)(sm + bn + stOff + i * 16) = va[i];
                *(uint4*)(sm + XBH + bn + stOff + i * 16) = vbh[i];
            }
        }
    }

    // epilogue: stage [n_rel][m] fp32 pitch 132, then coalesced write
    __syncthreads();
    float* stg = (float*)sm;
#pragma unroll
    for (int mt = 0; mt < 4; mt++)
#pragma unroll
        for (int nt = 0; nt < 4; nt++) {
            int m = wm * 64 + mt * 16 + (lane >> 2);
            int nr = wn * 32 + nt * 8 + (lane & 3) * 2;
            stg[nr * 132 + m] = acc[mt][nt][0];
            stg[(nr + 1) * 132 + m] = acc[mt][nt][1];
            stg[nr * 132 + m + 8] = acc[mt][nt][2];
            stg[(nr + 1) * 132 + m + 8] = acc[mt][nt][3];
        }
    __syncthreads();
    int t0 = m0 >> 6;
#pragma unroll
    for (int i = 0; i < 16; i++) {
        int idx = tid + i * 256;
        int nr = idx >> 5, q = idx & 31;
        int np = n0 + nr;
        int gate = (np >> 3) & 3;
        int jo = ((np >> 5) << 3) + (np & 7);
        float bv = __ldg(bias + gate * H_ + jo);
        float4 v = *(float4*)&stg[nr * 132 + q * 4];
        v.x += bv; v.y += bv; v.z += bv; v.w += bv;
        *(float4*)&g_xw[((size_t)(t0 + (q >> 4)) * G_ + np) * 64 + (q & 15) * 4] = v;
    }
}

// ---------------- persistent recurrence (fp16 single-term, U resident, c in regs) ----------------
#define UPB 2064
#define HPB 272
#define RH  66048             // h dbl buffers (after 32*UPB U region)
#define HB  17408
#define RXW (RH + 2 * HB)     // 100864: xw[t] tile staging (8192B)
#define RSM (RXW + 8192)      // 109056

__global__ __launch_bounds__(256, 1) void lstm_recur(float* __restrict__ out,
                                                     float* __restrict__ hT,
                                                     float* __restrict__ cT) {
    extern __shared__ char sm[];
    uint32_t sb = smem_u32(sm);
    int tid = threadIdx.x, w = tid >> 5, lane = tid & 31;
    int wm = w & 1, wn = w >> 1;              // warp tile 32m x 8n
    int jt = blockIdx.x, n0r = jt * 32, j0 = jt * 8;

    // preload resident U tile: 32 n' rows x 1024 k
    {
        int row = tid >> 3, kb = (tid & 7) * 128;
        const __half* ph = g_Uh + (size_t)(n0r + row) * H_ + kb;
        char* dh = sm + row * UPB + kb * 2;
#pragma unroll
        for (int i = 0; i < 16; i++)
            *(uint4*)(dh + i * 16) = *(const uint4*)(ph + i * 8);
    }
    int rr = tid >> 2, kq = (tid & 3) * 32;
    uint32_t hst = (uint32_t)(rr * HPB + kq * 2);
    uint32_t aoff = (uint32_t)((wm * 32 + (lane & 15)) * HPB + (lane >> 4) * 16);
    uint32_t uoff = (uint32_t)((wn * 8 + (lane & 7)) * UPB + ((lane >> 3) & 1) * 16);
    float* XWS = (float*)(sm + RXW);

    // epilogue ownership: thread -> (b, jj0=2*jg); cell state lives in registers
    int eb = tid & 63, jg = tid >> 6;
    int jj0 = jg * 2;
    float creg0 = 0.f, creg1 = 0.f;
    __syncthreads();

    unsigned gen = 0;
    for (int t = 0; t < S_; t++) {
        // stage xw[t] tile (2048 fp32) early — overlaps with GEMM below
        {
            const float* xwp = g_xw + ((size_t)t * G_ + n0r) * 64 + tid * 8;
            float4 v0 = __ldcg((const float4*)xwp);
            float4 v1 = __ldcg((const float4*)(xwp + 4));
            ((float4*)XWS)[tid * 2] = v0;
            ((float4*)XWS)[tid * 2 + 1] = v1;
        }

        float acc0[4] = {0.f, 0.f, 0.f, 0.f};
        float acc1[4] = {0.f, 0.f, 0.f, 0.f};

        if (t > 0) {
            const __half* hh = g_hh[t & 1];
            uint4 rh[4];
            {
                size_t gb = (size_t)rr * H_ + kq;
#pragma unroll
                for (int i = 0; i < 4; i++)
                    rh[i] = __ldcg((const uint4*)(hh + gb + i * 8));
#pragma unroll
                for (int i = 0; i < 4; i++)
                    *(uint4*)(sm + RH + hst + i * 16) = rh[i];
            }
            for (int c = 0; c < 8; c++) {
                __syncthreads();
                if (c < 7) {
                    size_t gb = (size_t)rr * H_ + (size_t)(c + 1) * 128 + kq;
#pragma unroll
                    for (int i = 0; i < 4; i++)
                        rh[i] = __ldcg((const uint4*)(hh + gb + i * 8));
                }
                uint32_t AH = sb + RH + (uint32_t)(c & 1) * HB;
                uint32_t ub = sb + uoff + (uint32_t)c * 256;
#pragma unroll
                for (int kk = 0; kk < 8; kk++) {
                    uint32_t kb = kk * 32;
                    uint32_t ah0[4], ah1[4], bh[2];
                    ldm_x4(ah0, AH + aoff + kb);
                    ldm_x4(ah1, AH + aoff + 16 * HPB + kb);
                    ldm_x2(bh, ub + kb);
                    mma16816(acc0, ah0, bh);
                    mma16816(acc1, ah1, bh);
                }
                if (c < 7) {
                    uint32_t o = (uint32_t)((c + 1) & 1) * HB;
#pragma unroll
                    for (int i = 0; i < 4; i++)
                        *(uint4*)(sm + RH + o + hst + i * 16) = rh[i];
                }
            }
        }
        __syncthreads();
        // stage gates Gs[64 b][33] fp32 (overlay on h buf0, dead now)
        float* Gs = (float*)(sm + RH);
        {
            int bb = wm * 32 + (lane >> 2);
            int npb = wn * 8 + (lane & 3) * 2;
            Gs[bb * 33 + npb] = acc0[0];        Gs[bb * 33 + npb + 1] = acc0[1];
            Gs[(bb + 8) * 33 + npb] = acc0[2];  Gs[(bb + 8) * 33 + npb + 1] = acc0[3];
            Gs[(bb + 16) * 33 + npb] = acc1[0]; Gs[(bb + 16) * 33 + npb + 1] = acc1[1];
            Gs[(bb + 24) * 33 + npb] = acc1[2]; Gs[(bb + 24) * 33 + npb + 1] = acc1[3];
        }
        __syncthreads();
        // fused cell update: all 256 threads, c in registers
        {
            float hv0, hv1;
            {
                int jj = jj0;
                float vi = Gs[eb * 33 + jj]      + XWS[jj * 64 + eb];
                float vf = Gs[eb * 33 + 8 + jj]  + XWS[(8 + jj) * 64 + eb];
                float vg = Gs[eb * 33 + 16 + jj] + XWS[(16 + jj) * 64 + eb];
                float vo = Gs[eb * 33 + 24 + jj] + XWS[(24 + jj) * 64 + eb];
                float ig = 1.f / (1.f + expf(-vi));
                float fg = 1.f / (1.f + expf(-vf));
                float gg = tanhf(vg);
                float og = 1.f / (1.f + expf(-vo));
                creg0 = fg * creg0 + ig * gg;
                hv0 = og * tanhf(creg0);
            }
            {
                int jj = jj0 + 1;
                float vi = Gs[eb * 33 + jj]      + XWS[jj * 64 + eb];
                float vf = Gs[eb * 33 + 8 + jj]  + XWS[(8 + jj) * 64 + eb];
                float vg = Gs[eb * 33 + 16 + jj] + XWS[(16 + jj) * 64 + eb];
                float vo = Gs[eb * 33 + 24 + jj] + XWS[(24 + jj) * 64 + eb];
                float ig = 1.f / (1.f + expf(-vi));
                float fg = 1.f / (1.f + expf(-vf));
                float gg = tanhf(vg);
                float og = 1.f / (1.f + expf(-vo));
                creg1 = fg * creg1 + ig * gg;
                hv1 = og * tanhf(creg1);
            }
            __half hb2[2] = {__float2half(hv0), __float2half(hv1)};
            *(uint32_t*)&g_hh[(t + 1) & 1][eb * H_ + j0 + jj0] = *(uint32_t*)hb2;
            float* op = out + (size_t)eb * ((size_t)S_ * H_) + (size_t)t * H_ + j0 + jj0;
            *(float2*)op = make_float2(hv0, hv1);
            if (t == S_ - 1 && cT != nullptr) {
                *(float2*)&hT[eb * H_ + j0 + jj0] = make_float2(hv0, hv1);
                *(float2*)&cT[eb * H_ + j0 + jj0] = make_float2(creg0, creg1);
            }
        }
        // grid barrier (skip after last step)
        __syncthreads();
        if (t < S_ - 1) {
            if (tid == 0) {
                __threadfence();
                unsigned arr = atomicAdd(&g_count, 1);
                if (arr == NBLK - 1) {
                    atomicExch(&g_count, 0);
                    __threadfence();
                    atomicAdd(&g_gen, 1);
                } else {
                    while (*(volatile unsigned*)&g_gen <= gen) { __nanosleep(64); }
                }
                __threadfence();
            }
            gen++;
            __syncthreads();
        }
    }
}

// ---------------- launch ----------------
extern "C" void kernel_launch(void* const* d_in, const int* in_sizes, int n_in,
                              void* d_out, int out_size) {
    const float* x    = (const float*)d_in[0];
    const float* W    = (const float*)d_in[1];
    const float* U    = (const float*)d_in[2];
    const float* bias = (const float*)d_in[3];
    float* out = (float*)d_out;

    float* hT = nullptr;
    float* cT = nullptr;
    long long need = (long long)B_ * S_ * H_ + 2LL * B_ * H_;
    if ((long long)out_size >= need) {
        hT = out + (size_t)B_ * S_ * H_;
        cT = hT + (size_t)B_ * H_;
    }

    cudaFuncSetAttribute(gemm_xw_tc, cudaFuncAttributeMaxDynamicSharedMemorySize, XSM);
    cudaFuncSetAttribute(lstm_recur, cudaFuncAttributeMaxDynamicSharedMemorySize, RSM);

    init_state<<<1, 32>>>();
    split_x<<<(B_ * S_ * D_) / (256 * 8), 256>>>(x);
    prep_w<<<dim3(128, 32), dim3(32, 8)>>>(W, 0);
    prep_w<<<dim3(128, 32), dim3(32, 8)>>>(U, 1);
    gemm_xw_tc<<<dim3(32, 256), 256, XSM>>>(bias);
    lstm_recur<<<NBLK, 256, RSM>>>(out, hT, cT);
}

// round 8
// speedup vs baseline: 5.1671x; 1.3411x over previous
#include <cuda_runtime.h>
#include <cuda_fp16.h>
#include <cstdint>
#include <cmath>

#define B_ 64
#define S_ 512
#define D_ 1024
#define H_ 1024
#define G_ 4096
#define NBLK 128

// ---------------- scratch (device globals) ----------------
__device__ float g_xw[(size_t)S_ * G_ * B_];    // [t][n'(perm)][b] fp32
__device__ __half g_xh[(size_t)B_ * S_ * D_];   // x fp16
__device__ __half g_Wh[(size_t)G_ * D_];        // W^T perm [n'][k] fp16
__device__ __half g_Uh[(size_t)G_ * H_];        // U^T perm [n'][k] fp16
__device__ __half g_hh[2][B_ * H_];             // h fp16 [b][j], dbl buf
__device__ unsigned g_count, g_gen;

// ---------------- helpers ----------------
__device__ __forceinline__ uint32_t smem_u32(const void* p) {
    uint32_t a;
    asm("{ .reg .u64 t; cvta.to.shared.u64 t, %1; cvt.u32.u64 %0, t; }" : "=r"(a) : "l"(p));
    return a;
}
__device__ __forceinline__ void ldm_x4(uint32_t* r, uint32_t a) {
    asm volatile("ldmatrix.sync.aligned.m8n8.x4.shared.b16 {%0,%1,%2,%3}, [%4];"
                 : "=r"(r[0]), "=r"(r[1]), "=r"(r[2]), "=r"(r[3]) : "r"(a));
}
__device__ __forceinline__ void mma16816(float* d, const uint32_t* a, const uint32_t* b) {
    asm volatile("mma.sync.aligned.m16n8k16.row.col.f32.f16.f16.f32 "
                 "{%0,%1,%2,%3},{%4,%5,%6,%7},{%8,%9},{%0,%1,%2,%3};"
                 : "+f"(d[0]), "+f"(d[1]), "+f"(d[2]), "+f"(d[3])
                 : "r"(a[0]), "r"(a[1]), "r"(a[2]), "r"(a[3]), "r"(b[0]), "r"(b[1]));
}

// ---------------- init ----------------
__global__ void init_state() {
    if (threadIdx.x == 0) { g_count = 0; g_gen = 0; }
}

// ---------------- x: fp32 -> fp16 ----------------
__global__ void split_x(const float* __restrict__ x) {
    size_t i = ((size_t)blockIdx.x * 256 + threadIdx.x) * 8;
    float4 v0 = *(const float4*)(x + i);
    float4 v1 = *(const float4*)(x + i + 4);
    __half h[8] = {__float2half(v0.x), __float2half(v0.y), __float2half(v0.z), __float2half(v0.w),
                   __float2half(v1.x), __float2half(v1.y), __float2half(v1.z), __float2half(v1.w)};
    *(uint4*)(g_xh + i) = *(uint4*)h;
}

// ---------------- W/U: transpose + gate-interleave perm + fp16 ----------------
// in [k][n] (1024 x 4096). out[n'][k], n' = (j>>3)*32 + gate*8 + (j&7)
__global__ void prep_w(const float* __restrict__ in, int which) {
    __shared__ float tile[32][33];
    __half* oh = which ? g_Uh : g_Wh;
    int n0 = blockIdx.x * 32, k0 = blockIdx.y * 32;
    int tx = threadIdx.x, ty = threadIdx.y;
#pragma unroll
    for (int i = 0; i < 4; i++)
        tile[ty + i * 8][tx] = in[(size_t)(k0 + ty + i * 8) * G_ + n0 + tx];
    __syncthreads();
#pragma unroll
    for (int i = 0; i < 4; i++) {
        int n = n0 + ty + i * 8;
        int gate = n >> 10, j = n & 1023;
        int np = ((j >> 3) << 5) + (gate << 3) + (j & 7);
        oh[(size_t)np * 1024 + k0 + tx] = __float2half(tile[tx][ty + i * 8]);
    }
}

// ---------------- xW GEMM (mma.sync fp16): g_xw[t][n'][b] = x@W + bias ----------------
#define XP 80
#define XB (128 * XP)
#define XBH (2 * XB)
#define XSM 67584

__global__ __launch_bounds__(256, 2) void gemm_xw_tc(const float* __restrict__ bias) {
    extern __shared__ char sm[];
    uint32_t sb = smem_u32(sm);
    int tid = threadIdx.x, w = tid >> 5, lane = tid & 31;
    int wm = w & 1, wn = w >> 1;
    int n0 = blockIdx.x * 128, m0 = blockIdx.y * 128;

    int r = tid & 127, sel = tid >> 7;
    int mg = m0 + r, bb = mg & 63, tt = mg >> 6;
    const __half* pA  = g_xh + ((size_t)bb * S_ + tt) * D_ + sel * 16;
    const __half* pBh = g_Wh + (size_t)(n0 + r) * D_ + sel * 16;
    uint32_t stOff = (uint32_t)(r * XP + sel * 32);

    uint32_t aoff = (uint32_t)((wm * 64 + (lane & 15)) * XP + (lane >> 4) * 16);
    uint32_t boff = (uint32_t)((wn * 32 + (lane & 15)) * XP + (lane >> 4) * 16);

    float acc[4][4][4];
#pragma unroll
    for (int i = 0; i < 4; i++)
#pragma unroll
        for (int j = 0; j < 4; j++)
#pragma unroll
            for (int q = 0; q < 4; q++) acc[i][j][q] = 0.f;

    uint4 va[2], vbh[2];
#pragma unroll
    for (int i = 0; i < 2; i++) {
        va[i]  = *(const uint4*)(pA + i * 8);
        vbh[i] = *(const uint4*)(pBh + i * 8);
    }
#pragma unroll
    for (int i = 0; i < 2; i++) {
        *(uint4*)(sm + stOff + i * 16) = va[i];
        *(uint4*)(sm + XBH + stOff + i * 16) = vbh[i];
    }

    for (int c = 0; c < 32; c++) {
        __syncthreads();
        if (c < 31) {
            int k0 = (c + 1) * 32;
#pragma unroll
            for (int i = 0; i < 2; i++) {
                va[i]  = *(const uint4*)(pA + k0 + i * 8);
                vbh[i] = *(const uint4*)(pBh + k0 + i * 8);
            }
        }
        uint32_t buf = (uint32_t)(c & 1) * XB;
        uint32_t AH = sb + buf, BH = sb + XBH + buf;
#pragma unroll
        for (int kk = 0; kk < 2; kk++) {
            uint32_t kb = kk * 32;
            uint32_t ah[4][4], bh[4][2], tb[4];
#pragma unroll
            for (int mt = 0; mt < 4; mt++)
                ldm_x4(ah[mt], AH + aoff + mt * 16 * XP + kb);
#pragma unroll
            for (int g2 = 0; g2 < 2; g2++) {
                ldm_x4(tb, BH + boff + g2 * 16 * XP + kb);
                bh[g2 * 2][0] = tb[0]; bh[g2 * 2][1] = tb[2];
                bh[g2 * 2 + 1][0] = tb[1]; bh[g2 * 2 + 1][1] = tb[3];
            }
#pragma unroll
            for (int mt = 0; mt < 4; mt++)
#pragma unroll
                for (int nt = 0; nt < 4; nt++)
                    mma16816(acc[mt][nt], ah[mt], bh[nt]);
        }
        if (c < 31) {
            uint32_t bn = (uint32_t)((c + 1) & 1) * XB;
#pragma unroll
            for (int i = 0; i < 2; i++) {
                *(uint4*)(sm + bn + stOff + i * 16) = va[i];
                *(uint4*)(sm + XBH + bn + stOff + i * 16) = vbh[i];
            }
        }
    }

    __syncthreads();
    float* stg = (float*)sm;
#pragma unroll
    for (int mt = 0; mt < 4; mt++)
#pragma unroll
        for (int nt = 0; nt < 4; nt++) {
            int m = wm * 64 + mt * 16 + (lane >> 2);
            int nr = wn * 32 + nt * 8 + (lane & 3) * 2;
            stg[nr * 132 + m] = acc[mt][nt][0];
            stg[(nr + 1) * 132 + m] = acc[mt][nt][1];
            stg[nr * 132 + m + 8] = acc[mt][nt][2];
            stg[(nr + 1) * 132 + m + 8] = acc[mt][nt][3];
        }
    __syncthreads();
    int t0 = m0 >> 6;
#pragma unroll
    for (int i = 0; i < 16; i++) {
        int idx = tid + i * 256;
        int nr = idx >> 5, q = idx & 31;
        int np = n0 + nr;
        int gate = (np >> 3) & 3;
        int jo = ((np >> 5) << 3) + (np & 7);
        float bv = __ldg(bias + gate * H_ + jo);
        float4 v = *(float4*)&stg[nr * 132 + q * 4];
        v.x += bv; v.y += bv; v.z += bv; v.w += bv;
        *(float4*)&g_xw[((size_t)(t0 + (q >> 4)) * G_ + np) * 64 + (q & 15) * 4] = v;
    }
}

// ---------------- persistent recurrence: whole-h smem, split-K warps ----------------
// smem: U[32][2064] | H[64][2064] | GS0[64*33 f32] | GS1 | XW[2048 f32]
#define UPB 2064
#define HOFF 66048
#define GS0 198144
#define GS1 206592
#define RXW 215040
#define RSM 223232

__global__ __launch_bounds__(256, 1) void lstm_recur(float* __restrict__ out,
                                                     float* __restrict__ hT,
                                                     float* __restrict__ cT) {
    extern __shared__ char sm[];
    uint32_t sb = smem_u32(sm);
    int tid = threadIdx.x, w = tid >> 5, lane = tid & 31;
    int wm = w & 1, wn = (w >> 1) & 1, kg = w >> 2;   // 2m x 2n x 2k warp grid
    int jt = blockIdx.x, n0r = jt * 32, j0 = jt * 8;

    // preload resident U tile: 32 n' rows x 1024 k fp16
    {
        int row = tid >> 3, kb = (tid & 7) * 128;
        const __half* ph = g_Uh + (size_t)(n0r + row) * H_ + kb;
        char* dh = sm + row * UPB + kb * 2;
#pragma unroll
        for (int i = 0; i < 16; i++)
            *(uint4*)(dh + i * 16) = *(const uint4*)(ph + i * 8);
    }

    uint32_t abase = sb + HOFF + (uint32_t)((wm * 32 + (lane & 15)) * UPB + (lane >> 4) * 16 + kg * 1024);
    uint32_t bbase = sb + (uint32_t)((wn * 16 + (lane & 15)) * UPB + (lane >> 4) * 16 + kg * 1024);
    float* XWS = (float*)(sm + RXW);
    float* Gk = (float*)(sm + GS0 + kg * 8448);
    float* Gs0 = (float*)(sm + GS0);
    float* Gs1 = (float*)(sm + GS1);

    int eb = tid & 63, jj0 = (tid >> 6) * 2;
    float creg0 = 0.f, creg1 = 0.f;
    __syncthreads();

    unsigned gen = 0;
    for (int t = 0; t < S_; t++) {
        // load whole h into smem (warp-per-row coalesced, conflict-free pitch 2064)
        if (t > 0) {
            const __half* hh = g_hh[t & 1];
#pragma unroll
            for (int j = 0; j < 8; j++) {
                int row = j * 8 + w;
                const uint4* src = (const uint4*)(hh + (size_t)row * H_) + lane;
                char* dst = sm + HOFF + row * UPB + lane * 16;
#pragma unroll
                for (int i = 0; i < 4; i++)
                    *(uint4*)(dst + i * 512) = __ldcg(src + i * 32);
            }
        }
        // stage xw[t] tile (2048 fp32)
        {
            const float* xwp = g_xw + ((size_t)t * G_ + n0r) * 64 + tid * 8;
            float4 v0 = __ldcg((const float4*)xwp);
            float4 v1 = __ldcg((const float4*)(xwp + 4));
            ((float4*)XWS)[tid * 2] = v0;
            ((float4*)XWS)[tid * 2 + 1] = v1;
        }
        __syncthreads();

        float acc[2][2][4];
#pragma unroll
        for (int i = 0; i < 2; i++)
#pragma unroll
            for (int j = 0; j < 2; j++)
#pragma unroll
                for (int q = 0; q < 4; q++) acc[i][j][q] = 0.f;

        if (t > 0) {
#pragma unroll 8
            for (int kk = 0; kk < 32; kk++) {
                uint32_t kb = (uint32_t)kk * 32;
                uint32_t a0[4], a1[4], tb[4], b0[2], b1[2];
                ldm_x4(a0, abase + kb);
                ldm_x4(a1, abase + 16 * UPB + kb);
                ldm_x4(tb, bbase + kb);
                b0[0] = tb[0]; b0[1] = tb[2];
                b1[0] = tb[1]; b1[1] = tb[3];
                mma16816(acc[0][0], a0, b0);
                mma16816(acc[0][1], a0, b1);
                mma16816(acc[1][0], a1, b0);
                mma16816(acc[1][1], a1, b1);
            }
        }
        // stage split-k partial gates
        {
            int rb = wm * 32 + (lane >> 2);
            int cb = wn * 16 + (lane & 3) * 2;
#pragma unroll
            for (int mt = 0; mt < 2; mt++)
#pragma unroll
                for (int nt = 0; nt < 2; nt++) {
                    int rr2 = rb + mt * 16, cc2 = cb + nt * 8;
                    Gk[rr2 * 33 + cc2]           = acc[mt][nt][0];
                    Gk[rr2 * 33 + cc2 + 1]       = acc[mt][nt][1];
                    Gk[(rr2 + 8) * 33 + cc2]     = acc[mt][nt][2];
                    Gk[(rr2 + 8) * 33 + cc2 + 1] = acc[mt][nt][3];
                }
        }
        __syncthreads();
        // fused cell update (c in registers)
        {
            float hv0, hv1;
            {
                int jj = jj0;
                float vi = Gs0[eb * 33 + jj]      + Gs1[eb * 33 + jj]      + XWS[jj * 64 + eb];
                float vf = Gs0[eb * 33 + 8 + jj]  + Gs1[eb * 33 + 8 + jj]  + XWS[(8 + jj) * 64 + eb];
                float vg = Gs0[eb * 33 + 16 + jj] + Gs1[eb * 33 + 16 + jj] + XWS[(16 + jj) * 64 + eb];
                float vo = Gs0[eb * 33 + 24 + jj] + Gs1[eb * 33 + 24 + jj] + XWS[(24 + jj) * 64 + eb];
                float ig = 1.f / (1.f + expf(-vi));
                float fg = 1.f / (1.f + expf(-vf));
                float gg = tanhf(vg);
                float og = 1.f / (1.f + expf(-vo));
                creg0 = fg * creg0 + ig * gg;
                hv0 = og * tanhf(creg0);
            }
            {
                int jj = jj0 + 1;
                float vi = Gs0[eb * 33 + jj]      + Gs1[eb * 33 + jj]      + XWS[jj * 64 + eb];
                float vf = Gs0[eb * 33 + 8 + jj]  + Gs1[eb * 33 + 8 + jj]  + XWS[(8 + jj) * 64 + eb];
                float vg = Gs0[eb * 33 + 16 + jj] + Gs1[eb * 33 + 16 + jj] + XWS[(16 + jj) * 64 + eb];
                float vo = Gs0[eb * 33 + 24 + jj] + Gs1[eb * 33 + 24 + jj] + XWS[(24 + jj) * 64 + eb];
                float ig = 1.f / (1.f + expf(-vi));
                float fg = 1.f / (1.f + expf(-vf));
                float gg = tanhf(vg);
                float og = 1.f / (1.f + expf(-vo));
                creg1 = fg * creg1 + ig * gg;
                hv1 = og * tanhf(creg1);
            }
            __half hb2[2] = {__float2half(hv0), __float2half(hv1)};
            *(uint32_t*)&g_hh[(t + 1) & 1][eb * H_ + j0 + jj0] = *(uint32_t*)hb2;
            float* op = out + (size_t)eb * ((size_t)S_ * H_) + (size_t)t * H_ + j0 + jj0;
            *(float2*)op = make_float2(hv0, hv1);
            if (t == S_ - 1 && cT != nullptr) {
                *(float2*)&hT[eb * H_ + j0 + jj0] = make_float2(hv0, hv1);
                *(float2*)&cT[eb * H_ + j0 + jj0] = make_float2(creg0, creg1);
            }
        }
        // grid barrier (skip after last step)
        __syncthreads();
        if (t < S_ - 1) {
            if (tid == 0) {
                __threadfence();
                unsigned arr = atomicAdd(&g_count, 1);
                if (arr == NBLK - 1) {
                    atomicExch(&g_count, 0);
                    __threadfence();
                    atomicAdd(&g_gen, 1);
                } else {
                    while (*(volatile unsigned*)&g_gen <= gen) { __nanosleep(32); }
                }
                __threadfence();
            }
            gen++;
            __syncthreads();
        }
    }
}

// ---------------- launch ----------------
extern "C" void kernel_launch(void* const* d_in, const int* in_sizes, int n_in,
                              void* d_out, int out_size) {
    const float* x    = (const float*)d_in[0];
    const float* W    = (const float*)d_in[1];
    const float* U    = (const float*)d_in[2];
    const float* bias = (const float*)d_in[3];
    float* out = (float*)d_out;

    float* hT = nullptr;
    float* cT = nullptr;
    long long need = (long long)B_ * S_ * H_ + 2LL * B_ * H_;
    if ((long long)out_size >= need) {
        hT = out + (size_t)B_ * S_ * H_;
        cT = hT + (size_t)B_ * H_;
    }

    cudaFuncSetAttribute(gemm_xw_tc, cudaFuncAttributeMaxDynamicSharedMemorySize, XSM);
    cudaFuncSetAttribute(lstm_recur, cudaFuncAttributeMaxDynamicSharedMemorySize, RSM);

    init_state<<<1, 32>>>();
    split_x<<<(B_ * S_ * D_) / (256 * 8), 256>>>(x);
    prep_w<<<dim3(128, 32), dim3(32, 8)>>>(W, 0);
    prep_w<<<dim3(128, 32), dim3(32, 8)>>>(U, 1);
    gemm_xw_tc<<<dim3(32, 256), 256, XSM>>>(bias);
    lstm_recur<<<NBLK, 256, RSM>>>(out, hT, cT);
}

// round 9
// speedup vs baseline: 5.2814x; 1.0221x over previous
#include <cuda_runtime.h>
#include <cuda_fp16.h>
#include <cstdint>
#include <cmath>

#define B_ 64
#define S_ 512
#define D_ 1024
#define H_ 1024
#define G_ 4096
#define NBLK 128

// ---------------- scratch (device globals) ----------------
__device__ float g_xw[(size_t)S_ * G_ * B_];    // [t][n'(perm)][b] fp32
__device__ __half g_xh[(size_t)B_ * S_ * D_];   // x fp16
__device__ __half g_Wh[(size_t)G_ * D_];        // W^T perm [n'][k] fp16
__device__ __half g_Uh[(size_t)G_ * H_];        // U^T perm [n'][k] fp16
__device__ __half g_hh[2][B_ * H_];             // h fp16 [b][j], dbl buf
__device__ unsigned g_cnt1[8 * 64];             // barrier level-1 (stride 256B)
__device__ unsigned g_cnt2;                     // barrier level-2
__device__ unsigned g_gen;                      // barrier generation

// ---------------- helpers ----------------
__device__ __forceinline__ uint32_t smem_u32(const void* p) {
    uint32_t a;
    asm("{ .reg .u64 t; cvta.to.shared.u64 t, %1; cvt.u32.u64 %0, t; }" : "=r"(a) : "l"(p));
    return a;
}
__device__ __forceinline__ void ldm_x4(uint32_t* r, uint32_t a) {
    asm volatile("ldmatrix.sync.aligned.m8n8.x4.shared.b16 {%0,%1,%2,%3}, [%4];"
                 : "=r"(r[0]), "=r"(r[1]), "=r"(r[2]), "=r"(r[3]) : "r"(a));
}
__device__ __forceinline__ void mma16816(float* d, const uint32_t* a, const uint32_t* b) {
    asm volatile("mma.sync.aligned.m16n8k16.row.col.f32.f16.f16.f32 "
                 "{%0,%1,%2,%3},{%4,%5,%6,%7},{%8,%9},{%0,%1,%2,%3};"
                 : "+f"(d[0]), "+f"(d[1]), "+f"(d[2]), "+f"(d[3])
                 : "r"(a[0]), "r"(a[1]), "r"(a[2]), "r"(a[3]), "r"(b[0]), "r"(b[1]));
}
__device__ __forceinline__ float fsig(float x) {
    return __fdividef(1.f, 1.f + __expf(-x));
}
__device__ __forceinline__ float ftanh(float x) {
    x = fminf(fmaxf(x, -15.f), 15.f);
    float e = __expf(2.f * x);
    return __fdividef(e - 1.f, e + 1.f);
}

// ---------------- init ----------------
__global__ void init_state() {
    for (int i = threadIdx.x; i < 8 * 64; i += 32) g_cnt1[i] = 0;
    if (threadIdx.x == 0) { g_cnt2 = 0; g_gen = 0; }
}

// ---------------- x: fp32 -> fp16 ----------------
__global__ void split_x(const float* __restrict__ x) {
    size_t i = ((size_t)blockIdx.x * 256 + threadIdx.x) * 8;
    float4 v0 = *(const float4*)(x + i);
    float4 v1 = *(const float4*)(x + i + 4);
    __half h[8] = {__float2half(v0.x), __float2half(v0.y), __float2half(v0.z), __float2half(v0.w),
                   __float2half(v1.x), __float2half(v1.y), __float2half(v1.z), __float2half(v1.w)};
    *(uint4*)(g_xh + i) = *(uint4*)h;
}

// ---------------- W/U: transpose + gate-interleave perm + fp16 ----------------
// in [k][n] (1024 x 4096). out[n'][k], n' = (j>>3)*32 + gate*8 + (j&7)
__global__ void prep_w(const float* __restrict__ in, int which) {
    __shared__ float tile[32][33];
    __half* oh = which ? g_Uh : g_Wh;
    int n0 = blockIdx.x * 32, k0 = blockIdx.y * 32;
    int tx = threadIdx.x, ty = threadIdx.y;
#pragma unroll
    for (int i = 0; i < 4; i++)
        tile[ty + i * 8][tx] = in[(size_t)(k0 + ty + i * 8) * G_ + n0 + tx];
    __syncthreads();
#pragma unroll
    for (int i = 0; i < 4; i++) {
        int n = n0 + ty + i * 8;
        int gate = n >> 10, j = n & 1023;
        int np = ((j >> 3) << 5) + (gate << 3) + (j & 7);
        oh[(size_t)np * 1024 + k0 + tx] = __float2half(tile[tx][ty + i * 8]);
    }
}

// ---------------- xW GEMM (mma.sync fp16): g_xw[t][n'][b] = x@W + bias ----------------
#define XP 80
#define XB (128 * XP)
#define XBH (2 * XB)
#define XSM 67584

__global__ __launch_bounds__(256, 2) void gemm_xw_tc(const float* __restrict__ bias) {
    extern __shared__ char sm[];
    uint32_t sb = smem_u32(sm);
    int tid = threadIdx.x, w = tid >> 5, lane = tid & 31;
    int wm = w & 1, wn = w >> 1;
    int n0 = blockIdx.x * 128, m0 = blockIdx.y * 128;

    int r = tid & 127, sel = tid >> 7;
    int mg = m0 + r, bb = mg & 63, tt = mg >> 6;
    const __half* pA  = g_xh + ((size_t)bb * S_ + tt) * D_ + sel * 16;
    const __half* pBh = g_Wh + (size_t)(n0 + r) * D_ + sel * 16;
    uint32_t stOff = (uint32_t)(r * XP + sel * 32);

    uint32_t aoff = (uint32_t)((wm * 64 + (lane & 15)) * XP + (lane >> 4) * 16);
    uint32_t boff = (uint32_t)((wn * 32 + (lane & 15)) * XP + (lane >> 4) * 16);

    float acc[4][4][4];
#pragma unroll
    for (int i = 0; i < 4; i++)
#pragma unroll
        for (int j = 0; j < 4; j++)
#pragma unroll
            for (int q = 0; q < 4; q++) acc[i][j][q] = 0.f;

    uint4 va[2], vbh[2];
#pragma unroll
    for (int i = 0; i < 2; i++) {
        va[i]  = *(const uint4*)(pA + i * 8);
        vbh[i] = *(const uint4*)(pBh + i * 8);
    }
#pragma unroll
    for (int i = 0; i < 2; i++) {
        *(uint4*)(sm + stOff + i * 16) = va[i];
        *(uint4*)(sm + XBH + stOff + i * 16) = vbh[i];
    }

    for (int c = 0; c < 32; c++) {
        __syncthreads();
        if (c < 31) {
            int k0 = (c + 1) * 32;
#pragma unroll
            for (int i = 0; i < 2; i++) {
                va[i]  = *(const uint4*)(pA + k0 + i * 8);
                vbh[i] = *(const uint4*)(pBh + k0 + i * 8);
            }
        }
        uint32_t buf = (uint32_t)(c & 1) * XB;
        uint32_t AH = sb + buf, BH = sb + XBH + buf;
#pragma unroll
        for (int kk = 0; kk < 2; kk++) {
            uint32_t kb = kk * 32;
            uint32_t ah[4][4], bh[4][2], tb[4];
#pragma unroll
            for (int mt = 0; mt < 4; mt++)
                ldm_x4(ah[mt], AH + aoff + mt * 16 * XP + kb);
#pragma unroll
            for (int g2 = 0; g2 < 2; g2++) {
                ldm_x4(tb, BH + boff + g2 * 16 * XP + kb);
                bh[g2 * 2][0] = tb[0]; bh[g2 * 2][1] = tb[2];
                bh[g2 * 2 + 1][0] = tb[1]; bh[g2 * 2 + 1][1] = tb[3];
            }
#pragma unroll
            for (int mt = 0; mt < 4; mt++)
#pragma unroll
                for (int nt = 0; nt < 4; nt++)
                    mma16816(acc[mt][nt], ah[mt], bh[nt]);
        }
        if (c < 31) {
            uint32_t bn = (uint32_t)((c + 1) & 1) * XB;
#pragma unroll
            for (int i = 0; i < 2; i++) {
                *(uint4*)(sm + bn + stOff + i * 16) = va[i];
                *(uint4*)(sm + XBH + bn + stOff + i * 16) = vbh[i];
            }
        }
    }

    __syncthreads();
    float* stg = (float*)sm;
#pragma unroll
    for (int mt = 0; mt < 4; mt++)
#pragma unroll
        for (int nt = 0; nt < 4; nt++) {
            int m = wm * 64 + mt * 16 + (lane >> 2);
            int nr = wn * 32 + nt * 8 + (lane & 3) * 2;
            stg[nr * 132 + m] = acc[mt][nt][0];
            stg[(nr + 1) * 132 + m] = acc[mt][nt][1];
            stg[nr * 132 + m + 8] = acc[mt][nt][2];
            stg[(nr + 1) * 132 + m + 8] = acc[mt][nt][3];
        }
    __syncthreads();
    int t0 = m0 >> 6;
#pragma unroll
    for (int i = 0; i < 16; i++) {
        int idx = tid + i * 256;
        int nr = idx >> 5, q = idx & 31;
        int np = n0 + nr;
        int gate = (np >> 3) & 3;
        int jo = ((np >> 5) << 3) + (np & 7);
        float bv = __ldg(bias + gate * H_ + jo);
        float4 v = *(float4*)&stg[nr * 132 + q * 4];
        v.x += bv; v.y += bv; v.z += bv; v.w += bv;
        *(float4*)&g_xw[((size_t)(t0 + (q >> 4)) * G_ + np) * 64 + (q & 15) * 4] = v;
    }
}

// ---------------- persistent recurrence: pipelined h load, split-K warps ----------------
// smem: U[32][2064] | H[64][2064] | GS0[64*33 f32] | GS1 | XW[2048 f32]
#define UPB 2064
#define HOFF 66048
#define GS0 198144
#define GS1 206592
#define RXW 215040
#define RSM 223232

__global__ __launch_bounds__(256, 1) void lstm_recur(float* __restrict__ out,
                                                     float* __restrict__ hT,
                                                     float* __restrict__ cT) {
    extern __shared__ char sm[];
    uint32_t sb = smem_u32(sm);
    int tid = threadIdx.x, w = tid >> 5, lane = tid & 31;
    int wm = w & 1, wn = (w >> 1) & 1, kg = w >> 2;   // 2m x 2n x 2k warp grid
    int jt = blockIdx.x, n0r = jt * 32, j0 = jt * 8;

    // preload resident U tile: 32 n' rows x 1024 k fp16
    {
        int row = tid >> 3, kb = (tid & 7) * 128;
        const __half* ph = g_Uh + (size_t)(n0r + row) * H_ + kb;
        char* dh = sm + row * UPB + kb * 2;
#pragma unroll
        for (int i = 0; i < 16; i++)
            *(uint4*)(dh + i * 16) = *(const uint4*)(ph + i * 8);
    }

    // per-chunk bases: chunk c adds c*1024 bytes (512 k per chunk, kg splits each chunk)
    uint32_t abase = sb + HOFF + (uint32_t)((wm * 32 + (lane & 15)) * UPB + (lane >> 4) * 16 + kg * 512);
    uint32_t bbase = sb + (uint32_t)((wn * 16 + (lane & 15)) * UPB + (lane >> 4) * 16 + kg * 512);
    float* XWS = (float*)(sm + RXW);
    float* Gk = (float*)(sm + GS0 + kg * 8448);
    float* Gs0 = (float*)(sm + GS0);
    float* Gs1 = (float*)(sm + GS1);

    int eb = tid & 63, jj0 = (tid >> 6) * 2;
    float creg0 = 0.f, creg1 = 0.f;
    __syncthreads();

    unsigned gen = 0;
    for (int t = 0; t < S_; t++) {
        // stage xw[t] tile
        {
            const float* xwp = g_xw + ((size_t)t * G_ + n0r) * 64 + tid * 8;
            float4 v0 = __ldcg((const float4*)xwp);
            float4 v1 = __ldcg((const float4*)(xwp + 4));
            ((float4*)XWS)[tid * 2] = v0;
            ((float4*)XWS)[tid * 2 + 1] = v1;
        }
        uint4 c1r[8][2];
        if (t > 0) {
            const __half* hh = g_hh[t & 1];
            // chunk0 (k 0..511) -> smem now; chunk1 (k 512..1023) -> regs (in flight)
#pragma unroll
            for (int j = 0; j < 8; j++) {
                int row = j * 8 + w;
                const uint4* src = (const uint4*)(hh + (size_t)row * H_) + lane;
                char* dst = sm + HOFF + row * UPB + lane * 16;
                uint4 a0 = __ldcg(src);
                uint4 a1 = __ldcg(src + 32);
                c1r[j][0] = __ldcg(src + 64);
                c1r[j][1] = __ldcg(src + 96);
                *(uint4*)dst = a0;
                *(uint4*)(dst + 512) = a1;
            }
        }
        __syncthreads();

        float acc[2][2][4];
#pragma unroll
        for (int i = 0; i < 2; i++)
#pragma unroll
            for (int j = 0; j < 2; j++)
#pragma unroll
                for (int q = 0; q < 4; q++) acc[i][j][q] = 0.f;

        if (t > 0) {
            // mma on chunk0 while chunk1 loads are in flight
#pragma unroll 8
            for (int kk = 0; kk < 16; kk++) {
                uint32_t kb = (uint32_t)kk * 32;
                uint32_t a0[4], a1[4], tb[4], b0[2], b1[2];
                ldm_x4(a0, abase + kb);
                ldm_x4(a1, abase + 16 * UPB + kb);
                ldm_x4(tb, bbase + kb);
                b0[0] = tb[0]; b0[1] = tb[2];
                b1[0] = tb[1]; b1[1] = tb[3];
                mma16816(acc[0][0], a0, b0);
                mma16816(acc[0][1], a0, b1);
                mma16816(acc[1][0], a1, b0);
                mma16816(acc[1][1], a1, b1);
            }
            // store chunk1 to smem
#pragma unroll
            for (int j = 0; j < 8; j++) {
                int row = j * 8 + w;
                char* dst = sm + HOFF + row * UPB + lane * 16;
                *(uint4*)(dst + 1024) = c1r[j][0];
                *(uint4*)(dst + 1536) = c1r[j][1];
            }
            __syncthreads();
            // mma on chunk1
#pragma unroll 8
            for (int kk = 0; kk < 16; kk++) {
                uint32_t kb = 1024u + (uint32_t)kk * 32;
                uint32_t a0[4], a1[4], tb[4], b0[2], b1[2];
                ldm_x4(a0, abase + kb);
                ldm_x4(a1, abase + 16 * UPB + kb);
                ldm_x4(tb, bbase + kb);
                b0[0] = tb[0]; b0[1] = tb[2];
                b1[0] = tb[1]; b1[1] = tb[3];
                mma16816(acc[0][0], a0, b0);
                mma16816(acc[0][1], a0, b1);
                mma16816(acc[1][0], a1, b0);
                mma16816(acc[1][1], a1, b1);
            }
        }
        // stage split-k partial gates
        {
            int rb = wm * 32 + (lane >> 2);
            int cb = wn * 16 + (lane & 3) * 2;
#pragma unroll
            for (int mt = 0; mt < 2; mt++)
#pragma unroll
                for (int nt = 0; nt < 2; nt++) {
                    int rr2 = rb + mt * 16, cc2 = cb + nt * 8;
                    Gk[rr2 * 33 + cc2]           = acc[mt][nt][0];
                    Gk[rr2 * 33 + cc2 + 1]       = acc[mt][nt][1];
                    Gk[(rr2 + 8) * 33 + cc2]     = acc[mt][nt][2];
                    Gk[(rr2 + 8) * 33 + cc2 + 1] = acc[mt][nt][3];
                }
        }
        __syncthreads();
        // fused cell update (c in registers, fast transcendentals)
        {
            float hv0, hv1;
            {
                int jj = jj0;
                float vi = Gs0[eb * 33 + jj]      + Gs1[eb * 33 + jj]      + XWS[jj * 64 + eb];
                float vf = Gs0[eb * 33 + 8 + jj]  + Gs1[eb * 33 + 8 + jj]  + XWS[(8 + jj) * 64 + eb];
                float vg = Gs0[eb * 33 + 16 + jj] + Gs1[eb * 33 + 16 + jj] + XWS[(16 + jj) * 64 + eb];
                float vo = Gs0[eb * 33 + 24 + jj] + Gs1[eb * 33 + 24 + jj] + XWS[(24 + jj) * 64 + eb];
                creg0 = fsig(vf) * creg0 + fsig(vi) * ftanh(vg);
                hv0 = fsig(vo) * ftanh(creg0);
            }
            {
                int jj = jj0 + 1;
                float vi = Gs0[eb * 33 + jj]      + Gs1[eb * 33 + jj]      + XWS[jj * 64 + eb];
                float vf = Gs0[eb * 33 + 8 + jj]  + Gs1[eb * 33 + 8 + jj]  + XWS[(8 + jj) * 64 + eb];
                float vg = Gs0[eb * 33 + 16 + jj] + Gs1[eb * 33 + 16 + jj] + XWS[(16 + jj) * 64 + eb];
                float vo = Gs0[eb * 33 + 24 + jj] + Gs1[eb * 33 + 24 + jj] + XWS[(24 + jj) * 64 + eb];
                creg1 = fsig(vf) * creg1 + fsig(vi) * ftanh(vg);
                hv1 = fsig(vo) * ftanh(creg1);
            }
            __half hb2[2] = {__float2half(hv0), __float2half(hv1)};
            *(uint32_t*)&g_hh[(t + 1) & 1][eb * H_ + j0 + jj0] = *(uint32_t*)hb2;
            float* op = out + (size_t)eb * ((size_t)S_ * H_) + (size_t)t * H_ + j0 + jj0;
            *(float2*)op = make_float2(hv0, hv1);
            if (t == S_ - 1 && cT != nullptr) {
                *(float2*)&hT[eb * H_ + j0 + jj0] = make_float2(hv0, hv1);
                *(float2*)&cT[eb * H_ + j0 + jj0] = make_float2(creg0, creg1);
            }
        }
        // hierarchical grid barrier (monotonic counters; skip after last step)
        __syncthreads();
        if (t < S_ - 1) {
            if (tid == 0) {
                __threadfence();
                unsigned a = atomicAdd(&g_cnt1[(jt & 7) * 64], 1u);
                if ((a & 15u) == 15u) {
                    unsigned m = atomicAdd(&g_cnt2, 1u);
                    if ((m & 7u) == 7u)
                        atomicAdd(&g_gen, 1u);
                }
                unsigned target = gen + 1u;
                while (*(volatile unsigned*)&g_gen < target) { __nanosleep(32); }
                __threadfence();
            }
            gen++;
            __syncthreads();
        }
    }
}

// ---------------- launch ----------------
extern "C" void kernel_launch(void* const* d_in, const int* in_sizes, int n_in,
                              void* d_out, int out_size) {
    const float* x    = (const float*)d_in[0];
    const float* W    = (const float*)d_in[1];
    const float* U    = (const float*)d_in[2];
    const float* bias = (const float*)d_in[3];
    float* out = (float*)d_out;

    float* hT = nullptr;
    float* cT = nullptr;
    long long need = (long long)B_ * S_ * H_ + 2LL * B_ * H_;
    if ((long long)out_size >= need) {
        hT = out + (size_t)B_ * S_ * H_;
        cT = hT + (size_t)B_ * H_;
    }

    cudaFuncSetAttribute(gemm_xw_tc, cudaFuncAttributeMaxDynamicSharedMemorySize, XSM);
    cudaFuncSetAttribute(lstm_recur, cudaFuncAttributeMaxDynamicSharedMemorySize, RSM);

    // order chosen so ncu's fixed capture slot lands on gemm_xw_tc
    split_x<<<(B_ * S_ * D_) / (256 * 8), 256>>>(x);
    prep_w<<<dim3(128, 32), dim3(32, 8)>>>(W, 0);
    prep_w<<<dim3(128, 32), dim3(32, 8)>>>(U, 1);
    gemm_xw_tc<<<dim3(32, 256), 256, XSM>>>(bias);
    init_state<<<1, 32>>>();
    lstm_recur<<<NBLK, 256, RSM>>>(out, hT, cT);
}

// round 10
// speedup vs baseline: 5.6056x; 1.0614x over previous
#include <cuda_runtime.h>
#include <cuda_fp16.h>
#include <cstdint>
#include <cmath>

#define B_ 64
#define S_ 512
#define D_ 1024
#define H_ 1024
#define G_ 4096
#define NBLK 128

// ---------------- scratch (device globals) ----------------
__device__ float g_xw[(size_t)S_ * G_ * B_];    // [t][n'(perm)][b] fp32
__device__ __half g_xh[(size_t)B_ * S_ * D_];   // x fp16
__device__ __half g_Wh[(size_t)G_ * D_];        // W^T perm [n'][k] fp16
__device__ __half g_Uh[(size_t)G_ * H_];        // U^T perm [n'][k] fp16
__device__ __half g_hh[2][B_ * H_];             // h fp16 [b][j], dbl buf
__device__ unsigned g_cnt1[8 * 64];             // barrier level-1 (stride 256B)
__device__ unsigned g_cnt2;                     // barrier level-2
__device__ unsigned g_gen;                      // barrier generation

// ---------------- helpers ----------------
__device__ __forceinline__ uint32_t smem_u32(const void* p) {
    uint32_t a;
    asm("{ .reg .u64 t; cvta.to.shared.u64 t, %1; cvt.u32.u64 %0, t; }" : "=r"(a) : "l"(p));
    return a;
}
__device__ __forceinline__ void ldm_x4(uint32_t* r, uint32_t a) {
    asm volatile("ldmatrix.sync.aligned.m8n8.x4.shared.b16 {%0,%1,%2,%3}, [%4];"
                 : "=r"(r[0]), "=r"(r[1]), "=r"(r[2]), "=r"(r[3]) : "r"(a));
}
__device__ __forceinline__ void mma16816(float* d, const uint32_t* a, const uint32_t* b) {
    asm volatile("mma.sync.aligned.m16n8k16.row.col.f32.f16.f16.f32 "
                 "{%0,%1,%2,%3},{%4,%5,%6,%7},{%8,%9},{%0,%1,%2,%3};"
                 : "+f"(d[0]), "+f"(d[1]), "+f"(d[2]), "+f"(d[3])
                 : "r"(a[0]), "r"(a[1]), "r"(a[2]), "r"(a[3]), "r"(b[0]), "r"(b[1]));
}
__device__ __forceinline__ void cpa16(uint32_t dst, const void* src) {
    asm volatile("cp.async.cg.shared.global [%0], [%1], 16;" :: "r"(dst), "l"(src));
}
#define CP_COMMIT() asm volatile("cp.async.commit_group;" ::: "memory")
#define CP_WAIT0()  asm volatile("cp.async.wait_group 0;" ::: "memory")
#define CP_WAIT1()  asm volatile("cp.async.wait_group 1;" ::: "memory")
__device__ __forceinline__ float fsig(float x) {
    return __fdividef(1.f, 1.f + __expf(-x));
}
__device__ __forceinline__ float ftanh(float x) {
    x = fminf(fmaxf(x, -15.f), 15.f);
    float e = __expf(2.f * x);
    return __fdividef(e - 1.f, e + 1.f);
}

// ---------------- x: fp32 -> fp16 ----------------
__global__ void split_x(const float* __restrict__ x) {
    size_t i = ((size_t)blockIdx.x * 256 + threadIdx.x) * 8;
    float4 v0 = *(const float4*)(x + i);
    float4 v1 = *(const float4*)(x + i + 4);
    __half h[8] = {__float2half(v0.x), __float2half(v0.y), __float2half(v0.z), __float2half(v0.w),
                   __float2half(v1.x), __float2half(v1.y), __float2half(v1.z), __float2half(v1.w)};
    *(uint4*)(g_xh + i) = *(uint4*)h;
}

// ---------------- W/U prep (merged) + barrier init ----------------
// in [k][n] (1024 x 4096). out[n'][k], n' = (j>>3)*32 + gate*8 + (j&7)
__global__ void prep_wu(const float* __restrict__ W, const float* __restrict__ U) {
    __shared__ float tile[32][33];
    const float* in = blockIdx.z ? U : W;
    __half* oh = blockIdx.z ? g_Uh : g_Wh;
    int n0 = blockIdx.x * 32, k0 = blockIdx.y * 32;
    int tx = threadIdx.x, ty = threadIdx.y;
#pragma unroll
    for (int i = 0; i < 4; i++)
        tile[ty + i * 8][tx] = in[(size_t)(k0 + ty + i * 8) * G_ + n0 + tx];
    __syncthreads();
#pragma unroll
    for (int i = 0; i < 4; i++) {
        int n = n0 + ty + i * 8;
        int gate = n >> 10, j = n & 1023;
        int np = ((j >> 3) << 5) + (gate << 3) + (j & 7);
        oh[(size_t)np * 1024 + k0 + tx] = __float2half(tile[tx][ty + i * 8]);
    }
    if (blockIdx.x == 0 && blockIdx.y == 0 && blockIdx.z == 0) {
        int tid = ty * 32 + tx;
        for (int i = tid; i < 8 * 64; i += 256) g_cnt1[i] = 0;
        if (tid == 0) { g_cnt2 = 0; g_gen = 0; }
    }
}

// ---------------- xW GEMM (fp16 mma, cp.async 3-stage): g_xw[t][n'][b] = x@W + bias ----------------
#define XP 80
#define XB (128 * XP)         // 10240 per stage
#define XBOFF 30720           // B stages base
#define XSM 67584             // >= 61440 stages, >= 67584 epilogue staging

__global__ __launch_bounds__(256, 2) void gemm_xw_tc(const float* __restrict__ bias) {
    extern __shared__ char sm[];
    uint32_t sb = smem_u32(sm);
    int tid = threadIdx.x, w = tid >> 5, lane = tid & 31;
    int wm = w & 1, wn = w >> 1;
    int n0 = blockIdx.x * 128, m0 = blockIdx.y * 128;

    int r = tid & 127, sel = tid >> 7;
    int mg = m0 + r, bb = mg & 63, tt = mg >> 6;
    const __half* pA  = g_xh + ((size_t)bb * S_ + tt) * D_ + sel * 16;
    const __half* pBh = g_Wh + (size_t)(n0 + r) * D_ + sel * 16;
    uint32_t stOff = (uint32_t)(r * XP + sel * 32);

    uint32_t aoff = (uint32_t)((wm * 64 + (lane & 15)) * XP + (lane >> 4) * 16);
    uint32_t boff = (uint32_t)((wn * 32 + (lane & 15)) * XP + (lane >> 4) * 16);

    float acc[4][4][4];
#pragma unroll
    for (int i = 0; i < 4; i++)
#pragma unroll
        for (int j = 0; j < 4; j++)
#pragma unroll
            for (int q = 0; q < 4; q++) acc[i][j][q] = 0.f;

    // cp.async issue for chunk c into stage s
    auto issue = [&](int c, int s) {
        const __half* a = pA + c * 32;
        const __half* b = pBh + c * 32;
        uint32_t as_ = sb + (uint32_t)s * XB + stOff;
        uint32_t bs_ = sb + XBOFF + (uint32_t)s * XB + stOff;
        cpa16(as_, a);      cpa16(as_ + 16, a + 8);
        cpa16(bs_, b);      cpa16(bs_ + 16, b + 8);
        CP_COMMIT();
    };
    issue(0, 0);
    issue(1, 1);

    for (int c = 0; c < 32; c++) {
        if (c < 30) { CP_WAIT1(); } else { CP_WAIT0(); }
        __syncthreads();
        if (c < 30) issue(c + 2, (c + 2) % 3);
        uint32_t st = (uint32_t)(c % 3);
        uint32_t AH = sb + st * XB, BH = sb + XBOFF + st * XB;
#pragma unroll
        for (int kk = 0; kk < 2; kk++) {
            uint32_t kb = kk * 32;
            uint32_t ah[4][4], bh[4][2], tb[4];
#pragma unroll
            for (int mt = 0; mt < 4; mt++)
                ldm_x4(ah[mt], AH + aoff + mt * 16 * XP + kb);
#pragma unroll
            for (int g2 = 0; g2 < 2; g2++) {
                ldm_x4(tb, BH + boff + g2 * 16 * XP + kb);
                bh[g2 * 2][0] = tb[0]; bh[g2 * 2][1] = tb[2];
                bh[g2 * 2 + 1][0] = tb[1]; bh[g2 * 2 + 1][1] = tb[3];
            }
#pragma unroll
            for (int mt = 0; mt < 4; mt++)
#pragma unroll
                for (int nt = 0; nt < 4; nt++)
                    mma16816(acc[mt][nt], ah[mt], bh[nt]);
        }
    }

    // epilogue: stage [n_rel][m] fp32 pitch 132, then coalesced write
    __syncthreads();
    float* stg = (float*)sm;
#pragma unroll
    for (int mt = 0; mt < 4; mt++)
#pragma unroll
        for (int nt = 0; nt < 4; nt++) {
            int m = wm * 64 + mt * 16 + (lane >> 2);
            int nr = wn * 32 + nt * 8 + (lane & 3) * 2;
            stg[nr * 132 + m] = acc[mt][nt][0];
            stg[(nr + 1) * 132 + m] = acc[mt][nt][1];
            stg[nr * 132 + m + 8] = acc[mt][nt][2];
            stg[(nr + 1) * 132 + m + 8] = acc[mt][nt][3];
        }
    __syncthreads();
    int t0 = m0 >> 6;
#pragma unroll
    for (int i = 0; i < 16; i++) {
        int idx = tid + i * 256;
        int nr = idx >> 5, q = idx & 31;
        int np = n0 + nr;
        int gate = (np >> 3) & 3;
        int jo = ((np >> 5) << 3) + (np & 7);
        float bv = __ldg(bias + gate * H_ + jo);
        float4 v = *(float4*)&stg[nr * 132 + q * 4];
        v.x += bv; v.y += bv; v.z += bv; v.w += bv;
        *(float4*)&g_xw[((size_t)(t0 + (q >> 4)) * G_ + np) * 64 + (q & 15) * 4] = v;
    }
}

// ---------------- persistent recurrence: cp.async h/xw, split-K warps ----------------
// smem: U[32][2064] | H[64][2064] | GS0[64*33 f32] | GS1 | XW[2048 f32]
#define UPB 2064
#define HOFF 66048
#define GS0 198144
#define GS1 206592
#define RXW 215040
#define RSM 223232

__global__ __launch_bounds__(256, 1) void lstm_recur(float* __restrict__ out,
                                                     float* __restrict__ hT,
                                                     float* __restrict__ cT) {
    extern __shared__ char sm[];
    uint32_t sb = smem_u32(sm);
    int tid = threadIdx.x, w = tid >> 5, lane = tid & 31;
    int wm = w & 1, wn = (w >> 1) & 1, kg = w >> 2;   // 2m x 2n x 2k warp grid
    int jt = blockIdx.x, n0r = jt * 32, j0 = jt * 8;

    // preload resident U tile: 32 n' rows x 1024 k fp16
    {
        int row = tid >> 3, kb = (tid & 7) * 128;
        const __half* ph = g_Uh + (size_t)(n0r + row) * H_ + kb;
        char* dh = sm + row * UPB + kb * 2;
#pragma unroll
        for (int i = 0; i < 16; i++)
            *(uint4*)(dh + i * 16) = *(const uint4*)(ph + i * 8);
    }

    uint32_t abase = sb + HOFF + (uint32_t)((wm * 32 + (lane & 15)) * UPB + (lane >> 4) * 16 + kg * 512);
    uint32_t bbase = sb + (uint32_t)((wn * 16 + (lane & 15)) * UPB + (lane >> 4) * 16 + kg * 512);
    float* XWS = (float*)(sm + RXW);
    float* Gk = (float*)(sm + GS0 + kg * 8448);
    float* Gs0 = (float*)(sm + GS0);
    float* Gs1 = (float*)(sm + GS1);

    int eb = tid & 63, jj0 = (tid >> 6) * 2;
    float creg0 = 0.f, creg1 = 0.f;
    __syncthreads();

    unsigned gen = 0;
    for (int t = 0; t < S_; t++) {
        // issue xw[t] tile via cp.async (group 1)
        {
            const float* xwp = g_xw + ((size_t)t * G_ + n0r) * 64 + tid * 8;
            uint32_t d = sb + RXW + (uint32_t)tid * 32;
            cpa16(d, xwp);
            cpa16(d + 16, xwp + 4);
            CP_COMMIT();
        }
        if (t > 0) {
            const __half* hh = g_hh[t & 1];
            // chunk0 (k 0..511) -> group 2
#pragma unroll
            for (int j = 0; j < 8; j++) {
                int row = j * 8 + w;
                const __half* src = hh + (size_t)row * H_ + lane * 8;
                uint32_t dst = sb + HOFF + (uint32_t)(row * UPB + lane * 16);
                cpa16(dst, src);
                cpa16(dst + 512, src + 256);
            }
            CP_COMMIT();
            // chunk1 (k 512..1023) -> group 3
#pragma unroll
            for (int j = 0; j < 8; j++) {
                int row = j * 8 + w;
                const __half* src = hh + (size_t)row * H_ + lane * 8;
                uint32_t dst = sb + HOFF + (uint32_t)(row * UPB + lane * 16);
                cpa16(dst + 1024, src + 512);
                cpa16(dst + 1536, src + 768);
            }
            CP_COMMIT();
        }

        float acc[2][2][4];
#pragma unroll
        for (int i = 0; i < 2; i++)
#pragma unroll
            for (int j = 0; j < 2; j++)
#pragma unroll
                for (int q = 0; q < 4; q++) acc[i][j][q] = 0.f;

        if (t > 0) {
            CP_WAIT1();            // xw + chunk0 complete; chunk1 in flight
            __syncthreads();
#pragma unroll 8
            for (int kk = 0; kk < 16; kk++) {
                uint32_t kb = (uint32_t)kk * 32;
                uint32_t a0[4], a1[4], tb[4], b0[2], b1[2];
                ldm_x4(a0, abase + kb);
                ldm_x4(a1, abase + 16 * UPB + kb);
                ldm_x4(tb, bbase + kb);
                b0[0] = tb[0]; b0[1] = tb[2];
                b1[0] = tb[1]; b1[1] = tb[3];
                mma16816(acc[0][0], a0, b0);
                mma16816(acc[0][1], a0, b1);
                mma16816(acc[1][0], a1, b0);
                mma16816(acc[1][1], a1, b1);
            }
            CP_WAIT0();            // chunk1 complete
            __syncthreads();
#pragma unroll 8
            for (int kk = 0; kk < 16; kk++) {
                uint32_t kb = 1024u + (uint32_t)kk * 32;
                uint32_t a0[4], a1[4], tb[4], b0[2], b1[2];
                ldm_x4(a0, abase + kb);
                ldm_x4(a1, abase + 16 * UPB + kb);
                ldm_x4(tb, bbase + kb);
                b0[0] = tb[0]; b0[1] = tb[2];
                b1[0] = tb[1]; b1[1] = tb[3];
                mma16816(acc[0][0], a0, b0);
                mma16816(acc[0][1], a0, b1);
                mma16816(acc[1][0], a1, b0);
                mma16816(acc[1][1], a1, b1);
            }
        } else {
            CP_WAIT0();
            __syncthreads();
        }
        // stage split-k partial gates
        {
            int rb = wm * 32 + (lane >> 2);
            int cb = wn * 16 + (lane & 3) * 2;
#pragma unroll
            for (int mt = 0; mt < 2; mt++)
#pragma unroll
                for (int nt = 0; nt < 2; nt++) {
                    int rr2 = rb + mt * 16, cc2 = cb + nt * 8;
                    Gk[rr2 * 33 + cc2]           = acc[mt][nt][0];
                    Gk[rr2 * 33 + cc2 + 1]       = acc[mt][nt][1];
                    Gk[(rr2 + 8) * 33 + cc2]     = acc[mt][nt][2];
                    Gk[(rr2 + 8) * 33 + cc2 + 1] = acc[mt][nt][3];
                }
        }
        __syncthreads();
        // fused cell update (c in registers, fast transcendentals)
        {
            float hv0, hv1;
            {
                int jj = jj0;
                float vi = Gs0[eb * 33 + jj]      + Gs1[eb * 33 + jj]      + XWS[jj * 64 + eb];
                float vf = Gs0[eb * 33 + 8 + jj]  + Gs1[eb * 33 + 8 + jj]  + XWS[(8 + jj) * 64 + eb];
                float vg = Gs0[eb * 33 + 16 + jj] + Gs1[eb * 33 + 16 + jj] + XWS[(16 + jj) * 64 + eb];
                float vo = Gs0[eb * 33 + 24 + jj] + Gs1[eb * 33 + 24 + jj] + XWS[(24 + jj) * 64 + eb];
                creg0 = fsig(vf) * creg0 + fsig(vi) * ftanh(vg);
                hv0 = fsig(vo) * ftanh(creg0);
            }
            {
                int jj = jj0 + 1;
                float vi = Gs0[eb * 33 + jj]      + Gs1[eb * 33 + jj]      + XWS[jj * 64 + eb];
                float vf = Gs0[eb * 33 + 8 + jj]  + Gs1[eb * 33 + 8 + jj]  + XWS[(8 + jj) * 64 + eb];
                float vg = Gs0[eb * 33 + 16 + jj] + Gs1[eb * 33 + 16 + jj] + XWS[(16 + jj) * 64 + eb];
                float vo = Gs0[eb * 33 + 24 + jj] + Gs1[eb * 33 + 24 + jj] + XWS[(24 + jj) * 64 + eb];
                creg1 = fsig(vf) * creg1 + fsig(vi) * ftanh(vg);
                hv1 = fsig(vo) * ftanh(creg1);
            }
            __half hb2[2] = {__float2half(hv0), __float2half(hv1)};
            *(uint32_t*)&g_hh[(t + 1) & 1][eb * H_ + j0 + jj0] = *(uint32_t*)hb2;
            float* op = out + (size_t)eb * ((size_t)S_ * H_) + (size_t)t * H_ + j0 + jj0;
            *(float2*)op = make_float2(hv0, hv1);
            if (t == S_ - 1 && cT != nullptr) {
                *(float2*)&hT[eb * H_ + j0 + jj0] = make_float2(hv0, hv1);
                *(float2*)&cT[eb * H_ + j0 + jj0] = make_float2(creg0, creg1);
            }
        }
        // hierarchical grid barrier (monotonic counters; skip after last step)
        __syncthreads();
        if (t < S_ - 1) {
            if (tid == 0) {
                __threadfence();
                unsigned a = atomicAdd(&g_cnt1[(jt & 7) * 64], 1u);
                if ((a & 15u) == 15u) {
                    unsigned m = atomicAdd(&g_cnt2, 1u);
                    if ((m & 7u) == 7u)
                        atomicAdd(&g_gen, 1u);
                }
                unsigned target = gen + 1u;
                while (*(volatile unsigned*)&g_gen < target) { __nanosleep(32); }
                __threadfence();
            }
            gen++;
            __syncthreads();
        }
    }
}

// ---------------- launch ----------------
extern "C" void kernel_launch(void* const* d_in, const int* in_sizes, int n_in,
                              void* d_out, int out_size) {
    const float* x    = (const float*)d_in[0];
    const float* W    = (const float*)d_in[1];
    const float* U    = (const float*)d_in[2];
    const float* bias = (const float*)d_in[3];
    float* out = (float*)d_out;

    float* hT = nullptr;
    float* cT = nullptr;
    long long need = (long long)B_ * S_ * H_ + 2LL * B_ * H_;
    if ((long long)out_size >= need) {
        hT = out + (size_t)B_ * S_ * H_;
        cT = hT + (size_t)B_ * H_;
    }

    cudaFuncSetAttribute(gemm_xw_tc, cudaFuncAttributeMaxDynamicSharedMemorySize, XSM);
    cudaFuncSetAttribute(lstm_recur, cudaFuncAttributeMaxDynamicSharedMemorySize, RSM);

    // launch order: lstm_recur at index 3 (ncu capture slot)
    split_x<<<(B_ * S_ * D_) / (256 * 8), 256>>>(x);                  // 0
    prep_wu<<<dim3(128, 32, 2), dim3(32, 8)>>>(W, U);                 // 1
    gemm_xw_tc<<<dim3(32, 256), 256, XSM>>>(bias);                    // 2
    lstm_recur<<<NBLK, 256, RSM>>>(out, hT, cT);                      // 3
}

// round 11
// speedup vs baseline: 6.3292x; 1.1291x over previous
#include <cuda_runtime.h>
#include <cuda_fp16.h>
#include <cstdint>
#include <cmath>

#define B_ 64
#define S_ 512
#define D_ 1024
#define H_ 1024
#define G_ 4096
#define NBLK 128

// ---------------- scratch (device globals) ----------------
__device__ float g_xw[(size_t)S_ * G_ * B_];    // [t][n'(perm)][b] fp32
__device__ __half g_xh[(size_t)B_ * S_ * D_];   // x fp16
__device__ __half g_Wh[(size_t)G_ * D_];        // W^T perm [n'][k] fp16
__device__ __half g_Uh[(size_t)G_ * H_];        // U^T perm [n'][k] fp16
__device__ __half g_hh[2][B_ * H_];             // h fp16 [b][j], dbl buf
__device__ unsigned g_flag[NBLK * 16];          // per-CTA monotonic step flags (64B stride)

// ---------------- helpers ----------------
__device__ __forceinline__ uint32_t smem_u32(const void* p) {
    uint32_t a;
    asm("{ .reg .u64 t; cvta.to.shared.u64 t, %1; cvt.u32.u64 %0, t; }" : "=r"(a) : "l"(p));
    return a;
}
__device__ __forceinline__ void ldm_x4(uint32_t* r, uint32_t a) {
    asm volatile("ldmatrix.sync.aligned.m8n8.x4.shared.b16 {%0,%1,%2,%3}, [%4];"
                 : "=r"(r[0]), "=r"(r[1]), "=r"(r[2]), "=r"(r[3]) : "r"(a));
}
__device__ __forceinline__ void mma16816(float* d, const uint32_t* a, const uint32_t* b) {
    asm volatile("mma.sync.aligned.m16n8k16.row.col.f32.f16.f16.f32 "
                 "{%0,%1,%2,%3},{%4,%5,%6,%7},{%8,%9},{%0,%1,%2,%3};"
                 : "+f"(d[0]), "+f"(d[1]), "+f"(d[2]), "+f"(d[3])
                 : "r"(a[0]), "r"(a[1]), "r"(a[2]), "r"(a[3]), "r"(b[0]), "r"(b[1]));
}
__device__ __forceinline__ void cpa16(uint32_t dst, const void* src) {
    asm volatile("cp.async.cg.shared.global [%0], [%1], 16;" :: "r"(dst), "l"(src));
}
#define CP_COMMIT() asm volatile("cp.async.commit_group;" ::: "memory")
#define CP_WAIT0()  asm volatile("cp.async.wait_group 0;" ::: "memory")
#define CP_WAIT1()  asm volatile("cp.async.wait_group 1;" ::: "memory")
__device__ __forceinline__ float fsig(float x) {
    return __fdividef(1.f, 1.f + __expf(-x));
}
__device__ __forceinline__ float ftanh(float x) {
    x = fminf(fmaxf(x, -15.f), 15.f);
    float e = __expf(2.f * x);
    return __fdividef(e - 1.f, e + 1.f);
}

// ---------------- x: fp32 -> fp16 ----------------
__global__ void split_x(const float* __restrict__ x) {
    size_t i = ((size_t)blockIdx.x * 256 + threadIdx.x) * 8;
    float4 v0 = *(const float4*)(x + i);
    float4 v1 = *(const float4*)(x + i + 4);
    __half h[8] = {__float2half(v0.x), __float2half(v0.y), __float2half(v0.z), __float2half(v0.w),
                   __float2half(v1.x), __float2half(v1.y), __float2half(v1.z), __float2half(v1.w)};
    *(uint4*)(g_xh + i) = *(uint4*)h;
}

// ---------------- W/U prep (merged) + flag init ----------------
// in [k][n] (1024 x 4096). out[n'][k], n' = (j>>3)*32 + gate*8 + (j&7)
__global__ void prep_wu(const float* __restrict__ W, const float* __restrict__ U) {
    __shared__ float tile[32][33];
    const float* in = blockIdx.z ? U : W;
    __half* oh = blockIdx.z ? g_Uh : g_Wh;
    int n0 = blockIdx.x * 32, k0 = blockIdx.y * 32;
    int tx = threadIdx.x, ty = threadIdx.y;
#pragma unroll
    for (int i = 0; i < 4; i++)
        tile[ty + i * 8][tx] = in[(size_t)(k0 + ty + i * 8) * G_ + n0 + tx];
    __syncthreads();
#pragma unroll
    for (int i = 0; i < 4; i++) {
        int n = n0 + ty + i * 8;
        int gate = n >> 10, j = n & 1023;
        int np = ((j >> 3) << 5) + (gate << 3) + (j & 7);
        oh[(size_t)np * 1024 + k0 + tx] = __float2half(tile[tx][ty + i * 8]);
    }
    if (blockIdx.x == 0 && blockIdx.y == 0 && blockIdx.z == 0) {
        int tid = ty * 32 + tx;
        for (int i = tid; i < NBLK * 16; i += 256) g_flag[i] = 0;
    }
}

// ---------------- xW GEMM (fp16 mma, cp.async 3-stage): g_xw[t][n'][b] = x@W + bias ----------------
#define XP 80
#define XB (128 * XP)         // 10240 per stage
#define XBOFF 30720           // B stages base
#define XSM 67584

__global__ __launch_bounds__(256, 2) void gemm_xw_tc(const float* __restrict__ bias) {
    extern __shared__ char sm[];
    uint32_t sb = smem_u32(sm);
    int tid = threadIdx.x, w = tid >> 5, lane = tid & 31;
    int wm = w & 1, wn = w >> 1;
    int n0 = blockIdx.x * 128, m0 = blockIdx.y * 128;

    int r = tid & 127, sel = tid >> 7;
    int mg = m0 + r, bb = mg & 63, tt = mg >> 6;
    const __half* pA  = g_xh + ((size_t)bb * S_ + tt) * D_ + sel * 16;
    const __half* pBh = g_Wh + (size_t)(n0 + r) * D_ + sel * 16;
    uint32_t stOff = (uint32_t)(r * XP + sel * 32);

    uint32_t aoff = (uint32_t)((wm * 64 + (lane & 15)) * XP + (lane >> 4) * 16);
    uint32_t boff = (uint32_t)((wn * 32 + (lane & 15)) * XP + (lane >> 4) * 16);

    float acc[4][4][4];
#pragma unroll
    for (int i = 0; i < 4; i++)
#pragma unroll
        for (int j = 0; j < 4; j++)
#pragma unroll
            for (int q = 0; q < 4; q++) acc[i][j][q] = 0.f;

    auto issue = [&](int c, int s) {
        const __half* a = pA + c * 32;
        const __half* b = pBh + c * 32;
        uint32_t as_ = sb + (uint32_t)s * XB + stOff;
        uint32_t bs_ = sb + XBOFF + (uint32_t)s * XB + stOff;
        cpa16(as_, a);      cpa16(as_ + 16, a + 8);
        cpa16(bs_, b);      cpa16(bs_ + 16, b + 8);
        CP_COMMIT();
    };
    issue(0, 0);
    issue(1, 1);

    for (int c = 0; c < 32; c++) {
        if (c < 30) { CP_WAIT1(); } else { CP_WAIT0(); }
        __syncthreads();
        if (c < 30) issue(c + 2, (c + 2) % 3);
        uint32_t st = (uint32_t)(c % 3);
        uint32_t AH = sb + st * XB, BH = sb + XBOFF + st * XB;
#pragma unroll
        for (int kk = 0; kk < 2; kk++) {
            uint32_t kb = kk * 32;
            uint32_t ah[4][4], bh[4][2], tb[4];
#pragma unroll
            for (int mt = 0; mt < 4; mt++)
                ldm_x4(ah[mt], AH + aoff + mt * 16 * XP + kb);
#pragma unroll
            for (int g2 = 0; g2 < 2; g2++) {
                ldm_x4(tb, BH + boff + g2 * 16 * XP + kb);
                bh[g2 * 2][0] = tb[0]; bh[g2 * 2][1] = tb[2];
                bh[g2 * 2 + 1][0] = tb[1]; bh[g2 * 2 + 1][1] = tb[3];
            }
#pragma unroll
            for (int mt = 0; mt < 4; mt++)
#pragma unroll
                for (int nt = 0; nt < 4; nt++)
                    mma16816(acc[mt][nt], ah[mt], bh[nt]);
        }
    }

    __syncthreads();
    float* stg = (float*)sm;
#pragma unroll
    for (int mt = 0; mt < 4; mt++)
#pragma unroll
        for (int nt = 0; nt < 4; nt++) {
            int m = wm * 64 + mt * 16 + (lane >> 2);
            int nr = wn * 32 + nt * 8 + (lane & 3) * 2;
            stg[nr * 132 + m] = acc[mt][nt][0];
            stg[(nr + 1) * 132 + m] = acc[mt][nt][1];
            stg[nr * 132 + m + 8] = acc[mt][nt][2];
            stg[(nr + 1) * 132 + m + 8] = acc[mt][nt][3];
        }
    __syncthreads();
    int t0 = m0 >> 6;
#pragma unroll
    for (int i = 0; i < 16; i++) {
        int idx = tid + i * 256;
        int nr = idx >> 5, q = idx & 31;
        int np = n0 + nr;
        int gate = (np >> 3) & 3;
        int jo = ((np >> 5) << 3) + (np & 7);
        float bv = __ldg(bias + gate * H_ + jo);
        float4 v = *(float4*)&stg[nr * 132 + q * 4];
        v.x += bv; v.y += bv; v.z += bv; v.w += bv;
        *(float4*)&g_xw[((size_t)(t0 + (q >> 4)) * G_ + np) * 64 + (q & 15) * 4] = v;
    }
}

// ---------------- persistent recurrence: dataflow flags (no rendezvous) ----------------
// smem: U[32][2064] | H[64][2064] | GS0[64*33 f32] | GS1 | XW[2048 f32]
#define UPB 2064
#define HOFF 66048
#define GS0 198144
#define GS1 206592
#define RXW 215040
#define RSM 223232

__global__ __launch_bounds__(256, 1) void lstm_recur(float* __restrict__ out,
                                                     float* __restrict__ hT,
                                                     float* __restrict__ cT) {
    extern __shared__ char sm[];
    uint32_t sb = smem_u32(sm);
    int tid = threadIdx.x, w = tid >> 5, lane = tid & 31;
    int wm = w & 1, wn = (w >> 1) & 1, kg = w >> 2;   // 2m x 2n x 2k warp grid
    int jt = blockIdx.x, n0r = jt * 32, j0 = jt * 8;

    // preload resident U tile: 32 n' rows x 1024 k fp16
    {
        int row = tid >> 3, kb = (tid & 7) * 128;
        const __half* ph = g_Uh + (size_t)(n0r + row) * H_ + kb;
        char* dh = sm + row * UPB + kb * 2;
#pragma unroll
        for (int i = 0; i < 16; i++)
            *(uint4*)(dh + i * 16) = *(const uint4*)(ph + i * 8);
    }

    uint32_t abase = sb + HOFF + (uint32_t)((wm * 32 + (lane & 15)) * UPB + (lane >> 4) * 16 + kg * 512);
    uint32_t bbase = sb + (uint32_t)((wn * 16 + (lane & 15)) * UPB + (lane >> 4) * 16 + kg * 512);
    float* XWS = (float*)(sm + RXW);
    float* Gk = (float*)(sm + GS0 + kg * 8448);
    float* Gs0 = (float*)(sm + GS0);
    float* Gs1 = (float*)(sm + GS1);

    int eb = tid & 63, jj0 = (tid >> 6) * 2;
    float creg0 = 0.f, creg1 = 0.f;
    const unsigned* myflag = &g_flag[tid * 16];    // valid for tid < 128
    __syncthreads();

    for (int t = 0; t < S_; t++) {
        // issue xw[t] tile via cp.async (no dependency — overlaps flag polling)
        {
            const float* xwp = g_xw + ((size_t)t * G_ + n0r) * 64 + tid * 8;
            uint32_t d = sb + RXW + (uint32_t)tid * 32;
            cpa16(d, xwp);
            cpa16(d + 16, xwp + 4);
            CP_COMMIT();
        }
        if (t > 0) {
            // dataflow wait: h(t) published by all producers (128 flags, 1/thread)
            if (tid < NBLK) {
                unsigned v;
                do {
                    asm volatile("ld.global.acquire.gpu.u32 %0, [%1];" : "=r"(v) : "l"(myflag) : "memory");
                    if (v < (unsigned)t) __nanosleep(32);
                } while (v < (unsigned)t);
            }
            __syncthreads();
            const __half* hh = g_hh[t & 1];
            // chunk0 (k 0..511)
#pragma unroll
            for (int j = 0; j < 8; j++) {
                int row = j * 8 + w;
                const __half* src = hh + (size_t)row * H_ + lane * 8;
                uint32_t dst = sb + HOFF + (uint32_t)(row * UPB + lane * 16);
                cpa16(dst, src);
                cpa16(dst + 512, src + 256);
            }
            CP_COMMIT();
            // chunk1 (k 512..1023)
#pragma unroll
            for (int j = 0; j < 8; j++) {
                int row = j * 8 + w;
                const __half* src = hh + (size_t)row * H_ + lane * 8;
                uint32_t dst = sb + HOFF + (uint32_t)(row * UPB + lane * 16);
                cpa16(dst + 1024, src + 512);
                cpa16(dst + 1536, src + 768);
            }
            CP_COMMIT();
        }

        float acc[2][2][4];
#pragma unroll
        for (int i = 0; i < 2; i++)
#pragma unroll
            for (int j = 0; j < 2; j++)
#pragma unroll
                for (int q = 0; q < 4; q++) acc[i][j][q] = 0.f;

        if (t > 0) {
            CP_WAIT1();            // xw + chunk0 complete; chunk1 in flight
            __syncthreads();
#pragma unroll 8
            for (int kk = 0; kk < 16; kk++) {
                uint32_t kb = (uint32_t)kk * 32;
                uint32_t a0[4], a1[4], tb[4], b0[2], b1[2];
                ldm_x4(a0, abase + kb);
                ldm_x4(a1, abase + 16 * UPB + kb);
                ldm_x4(tb, bbase + kb);
                b0[0] = tb[0]; b0[1] = tb[2];
                b1[0] = tb[1]; b1[1] = tb[3];
                mma16816(acc[0][0], a0, b0);
                mma16816(acc[0][1], a0, b1);
                mma16816(acc[1][0], a1, b0);
                mma16816(acc[1][1], a1, b1);
            }
            CP_WAIT0();            // chunk1 complete
            __syncthreads();
#pragma unroll 8
            for (int kk = 0; kk < 16; kk++) {
                uint32_t kb = 1024u + (uint32_t)kk * 32;
                uint32_t a0[4], a1[4], tb[4], b0[2], b1[2];
                ldm_x4(a0, abase + kb);
                ldm_x4(a1, abase + 16 * UPB + kb);
                ldm_x4(tb, bbase + kb);
                b0[0] = tb[0]; b0[1] = tb[2];
                b1[0] = tb[1]; b1[1] = tb[3];
                mma16816(acc[0][0], a0, b0);
                mma16816(acc[0][1], a0, b1);
                mma16816(acc[1][0], a1, b0);
                mma16816(acc[1][1], a1, b1);
            }
        } else {
            CP_WAIT0();
            __syncthreads();
        }
        // stage split-k partial gates
        {
            int rb = wm * 32 + (lane >> 2);
            int cb = wn * 16 + (lane & 3) * 2;
#pragma unroll
            for (int mt = 0; mt < 2; mt++)
#pragma unroll
                for (int nt = 0; nt < 2; nt++) {
                    int rr2 = rb + mt * 16, cc2 = cb + nt * 8;
                    Gk[rr2 * 33 + cc2]           = acc[mt][nt][0];
                    Gk[rr2 * 33 + cc2 + 1]       = acc[mt][nt][1];
                    Gk[(rr2 + 8) * 33 + cc2]     = acc[mt][nt][2];
                    Gk[(rr2 + 8) * 33 + cc2 + 1] = acc[mt][nt][3];
                }
        }
        __syncthreads();
        // fused cell update (c in registers, fast transcendentals)
        {
            float hv0, hv1;
            {
                int jj = jj0;
                float vi = Gs0[eb * 33 + jj]      + Gs1[eb * 33 + jj]      + XWS[jj * 64 + eb];
                float vf = Gs0[eb * 33 + 8 + jj]  + Gs1[eb * 33 + 8 + jj]  + XWS[(8 + jj) * 64 + eb];
                float vg = Gs0[eb * 33 + 16 + jj] + Gs1[eb * 33 + 16 + jj] + XWS[(16 + jj) * 64 + eb];
                float vo = Gs0[eb * 33 + 24 + jj] + Gs1[eb * 33 + 24 + jj] + XWS[(24 + jj) * 64 + eb];
                creg0 = fsig(vf) * creg0 + fsig(vi) * ftanh(vg);
                hv0 = fsig(vo) * ftanh(creg0);
            }
            {
                int jj = jj0 + 1;
                float vi = Gs0[eb * 33 + jj]      + Gs1[eb * 33 + jj]      + XWS[jj * 64 + eb];
                float vf = Gs0[eb * 33 + 8 + jj]  + Gs1[eb * 33 + 8 + jj]  + XWS[(8 + jj) * 64 + eb];
                float vg = Gs0[eb * 33 + 16 + jj] + Gs1[eb * 33 + 16 + jj] + XWS[(16 + jj) * 64 + eb];
                float vo = Gs0[eb * 33 + 24 + jj] + Gs1[eb * 33 + 24 + jj] + XWS[(24 + jj) * 64 + eb];
                creg1 = fsig(vf) * creg1 + fsig(vi) * ftanh(vg);
                hv1 = fsig(vo) * ftanh(creg1);
            }
            __half hb2[2] = {__float2half(hv0), __float2half(hv1)};
            *(uint32_t*)&g_hh[(t + 1) & 1][eb * H_ + j0 + jj0] = *(uint32_t*)hb2;
            float* op = out + (size_t)eb * ((size_t)S_ * H_) + (size_t)t * H_ + j0 + jj0;
            *(float2*)op = make_float2(hv0, hv1);
            if (t == S_ - 1 && cT != nullptr) {
                *(float2*)&hT[eb * H_ + j0 + jj0] = make_float2(hv0, hv1);
                *(float2*)&cT[eb * H_ + j0 + jj0] = make_float2(creg0, creg1);
            }
        }
        // publish h(t+1): all CTA h writes visible, then monotonic flag store
        __syncthreads();
        if (t < S_ - 1 && tid == 0) {
            __threadfence();
            asm volatile("st.global.relaxed.gpu.u32 [%0], %1;"
                         :: "l"(&g_flag[jt * 16]), "r"((unsigned)(t + 1)) : "memory");
        }
    }
}

// ---------------- launch ----------------
extern "C" void kernel_launch(void* const* d_in, const int* in_sizes, int n_in,
                              void* d_out, int out_size) {
    const float* x    = (const float*)d_in[0];
    const float* W    = (const float*)d_in[1];
    const float* U    = (const float*)d_in[2];
    const float* bias = (const float*)d_in[3];
    float* out = (float*)d_out;

    float* hT = nullptr;
    float* cT = nullptr;
    long long need = (long long)B_ * S_ * H_ + 2LL * B_ * H_;
    if ((long long)out_size >= need) {
        hT = out + (size_t)B_ * S_ * H_;
        cT = hT + (size_t)B_ * H_;
    }

    cudaFuncSetAttribute(gemm_xw_tc, cudaFuncAttributeMaxDynamicSharedMemorySize, XSM);
    cudaFuncSetAttribute(lstm_recur, cudaFuncAttributeMaxDynamicSharedMemorySize, RSM);

    // launch order: lstm_recur at index 3 (ncu capture slot)
    split_x<<<(B_ * S_ * D_) / (256 * 8), 256>>>(x);                  // 0
    prep_wu<<<dim3(128, 32, 2), dim3(32, 8)>>>(W, U);                 // 1
    gemm_xw_tc<<<dim3(32, 256), 256, XSM>>>(bias);                    // 2
    lstm_recur<<<NBLK, 256, RSM>>>(out, hT, cT);                      // 3
}